// round 10
// baseline (speedup 1.0000x reference)
#include <cuda_runtime.h>
#include <math.h>

// Problem constants
#define NBATCH 8
#define CCH    256
#define TSEQ   1024
#define NHEAD  8
#define HDIM   32

typedef unsigned long long u64;

// ---- packed f32x2 primitives (sm_100+) ----
__device__ __forceinline__ u64 bcast2(float x) {
    u64 r; asm("mov.b64 %0, {%1, %1};" : "=l"(r) : "f"(x)); return r;
}
__device__ __forceinline__ u64 fma2(u64 a, u64 b, u64 c) {
    u64 d; asm("fma.rn.f32x2 %0, %1, %2, %3;" : "=l"(d) : "l"(a), "l"(b), "l"(c));
    return d;
}
__device__ __forceinline__ u64 mul2(u64 a, u64 b) {
    u64 d; asm("mul.rn.f32x2 %0, %1, %2;" : "=l"(d) : "l"(a), "l"(b)); return d;
}
__device__ __forceinline__ u64 add2(u64 a, u64 b) {
    u64 d; asm("add.rn.f32x2 %0, %1, %2;" : "=l"(d) : "l"(a), "l"(b)); return d;
}
__device__ __forceinline__ float2 unpk2(u64 a) {
    float2 f; asm("mov.b64 {%0, %1}, %2;" : "=f"(f.x), "=f"(f.y) : "l"(a)); return f;
}

// ---- tf32 mma primitives ----
__device__ __forceinline__ unsigned tf32_of(float x) {
    unsigned r; asm("cvt.rna.tf32.f32 %0, %1;" : "=r"(r) : "f"(x)); return r;
}
__device__ __forceinline__ void tf32_split(float v, unsigned& hi, unsigned& lo) {
    hi = tf32_of(v);
    lo = tf32_of(v - __uint_as_float(hi));
}
__device__ __forceinline__ void mma_tf32(float c[4],
                                         unsigned a0, unsigned a1, unsigned a2, unsigned a3,
                                         unsigned b0, unsigned b1) {
    asm("mma.sync.aligned.m16n8k8.row.col.f32.tf32.tf32.f32 "
        "{%0,%1,%2,%3}, {%4,%5,%6,%7}, {%8,%9}, {%0,%1,%2,%3};"
        : "+f"(c[0]), "+f"(c[1]), "+f"(c[2]), "+f"(c[3])
        : "r"(a0), "r"(a1), "r"(a2), "r"(a3), "r"(b0), "r"(b1));
}

// Scratch. K/Q/V in [N, H, T, D].
__device__ float g_k[NBATCH * NHEAD * TSEQ * HDIM];
__device__ float g_q[NBATCH * NHEAD * TSEQ * HDIM];
__device__ float g_v[NBATCH * NHEAD * TSEQ * HDIM];
// attn output, TRANSPOSED [C, N*T], pre-split hi/lo (emitted by attn_reduce)
__device__ float g_attn_hi[CCH * NBATCH * TSEQ];
__device__ float g_attn_lo[CCH * NBATCH * TSEQ];
// Split-K partials
__device__ float g_pacc[64 * 36 * 32 * 128];
__device__ float g_plsum[64 * 36 * 128];
// Pre-split tf32 hi/lo of static GEMM inputs
__device__ float g_img_hi[NBATCH * CCH * TSEQ];
__device__ float g_img_lo[NBATCH * CCH * TSEQ];
__device__ float g_wk_hi[CCH * 3 * CCH];
__device__ float g_wk_lo[CCH * 3 * CCH];
__device__ float g_wm_hi[CCH * CCH];
__device__ float g_wm_lo[CCH * CCH];

#define AS_STRIDE 136
#define BS_STRIDE 72

// ---------------------------------------------------------------------------
// Kernel 0: pre-split image, w_kqv, w_mix into tf32 hi/lo arrays.
// 589824 float4 total = 2304 blocks x 256 threads.
// ---------------------------------------------------------------------------
#define IMG_F4 524288   // 2097152 / 4
#define WK_F4  49152    // 196608 / 4
#define WM_F4  16384    // 65536 / 4

__global__ __launch_bounds__(256) void presplit(const float* __restrict__ image,
                                                const float* __restrict__ wk,
                                                const float* __restrict__ wm) {
    int i = blockIdx.x * 256 + threadIdx.x;
    const float* src; float* dhi; float* dlo; int off;
    if (i < IMG_F4)                { src = image; dhi = g_img_hi; dlo = g_img_lo; off = i; }
    else if (i < IMG_F4 + WK_F4)   { src = wk;    dhi = g_wk_hi;  dlo = g_wk_lo;  off = i - IMG_F4; }
    else                           { src = wm;    dhi = g_wm_hi;  dlo = g_wm_lo;  off = i - IMG_F4 - WK_F4; }
    float4 v = ((const float4*)src)[off];
    unsigned h, l;
    float4 vh, vl;
    tf32_split(v.x, h, l); vh.x = __uint_as_float(h); vl.x = __uint_as_float(l);
    tf32_split(v.y, h, l); vh.y = __uint_as_float(h); vl.y = __uint_as_float(l);
    tf32_split(v.z, h, l); vh.z = __uint_as_float(h); vl.z = __uint_as_float(l);
    tf32_split(v.w, h, l); vh.w = __uint_as_float(h); vl.w = __uint_as_float(l);
    ((float4*)dhi)[off] = vh;
    ((float4*)dlo)[off] = vl;
}

// ---------------------------------------------------------------------------
// Kernel 1: KQV projection via 3xTF32 mma.sync, pre-split operands.
// ---------------------------------------------------------------------------
__global__ __launch_bounds__(256) void kqv_mma(const float* __restrict__ bias) {
    __shared__ float Ash[16 * AS_STRIDE];
    __shared__ float Asl[16 * AS_STRIDE];
    __shared__ float Bsh[16 * BS_STRIDE];
    __shared__ float Bsl[16 * BS_STRIDE];
    const int tid = threadIdx.x;
    const int lane = tid & 31;
    const int wid = tid >> 5;
    const int wm = wid & 3;
    const int wn = wid >> 2;
    const int g = lane >> 2, tig = lane & 3;
    const int bm = blockIdx.y * 128;
    const int bn = blockIdx.x * 64;
    const int n  = bm >> 10;
    const int t0 = bm & 1023;

    float c[2][4][4];
    #pragma unroll
    for (int am = 0; am < 2; am++)
        #pragma unroll
        for (int an = 0; an < 4; an++)
            #pragma unroll
            for (int i = 0; i < 4; i++) c[am][an][i] = 0.0f;

    float4 pah[2], pal[2], pbh, pbl;
    {
        #pragma unroll
        for (int l = 0; l < 2; l++) {
            int idx = l * 256 + tid;
            int k = idx >> 5, f = idx & 31;
            size_t gi = (size_t)n * 262144 + (size_t)k * 1024 + t0 + f * 4;
            pah[l] = *(const float4*)&g_img_hi[gi];
            pal[l] = *(const float4*)&g_img_lo[gi];
        }
        int k = tid >> 4, f = tid & 15;
        pbh = *(const float4*)&g_wk_hi[k * 768 + bn + f * 4];
        pbl = *(const float4*)&g_wk_lo[k * 768 + bn + f * 4];
    }

    for (int k0 = 0; k0 < 256; k0 += 16) {
        #pragma unroll
        for (int l = 0; l < 2; l++) {
            int idx = l * 256 + tid;
            int k = idx >> 5, f = idx & 31;
            *(float4*)&Ash[k * AS_STRIDE + f * 4] = pah[l];
            *(float4*)&Asl[k * AS_STRIDE + f * 4] = pal[l];
        }
        {
            int k = tid >> 4, f = tid & 15;
            *(float4*)&Bsh[k * BS_STRIDE + f * 4] = pbh;
            *(float4*)&Bsl[k * BS_STRIDE + f * 4] = pbl;
        }
        __syncthreads();
        if (k0 + 16 < 256) {
            #pragma unroll
            for (int l = 0; l < 2; l++) {
                int idx = l * 256 + tid;
                int k = idx >> 5, f = idx & 31;
                size_t gi = (size_t)n * 262144 + (size_t)(k0 + 16 + k) * 1024 + t0 + f * 4;
                pah[l] = *(const float4*)&g_img_hi[gi];
                pal[l] = *(const float4*)&g_img_lo[gi];
            }
            int k = tid >> 4, f = tid & 15;
            pbh = *(const float4*)&g_wk_hi[(k0 + 16 + k) * 768 + bn + f * 4];
            pbl = *(const float4*)&g_wk_lo[(k0 + 16 + k) * 768 + bn + f * 4];
        }
        #pragma unroll
        for (int ks = 0; ks < 16; ks += 8) {
            unsigned ahi[2][4], alo[2][4], bhi[4][2], blo[4][2];
            #pragma unroll
            for (int am = 0; am < 2; am++) {
                const int mb = wm * 32 + am * 16;
                ahi[am][0] = __float_as_uint(Ash[(ks + tig) * AS_STRIDE + mb + g]);
                ahi[am][1] = __float_as_uint(Ash[(ks + tig) * AS_STRIDE + mb + g + 8]);
                ahi[am][2] = __float_as_uint(Ash[(ks + tig + 4) * AS_STRIDE + mb + g]);
                ahi[am][3] = __float_as_uint(Ash[(ks + tig + 4) * AS_STRIDE + mb + g + 8]);
                alo[am][0] = __float_as_uint(Asl[(ks + tig) * AS_STRIDE + mb + g]);
                alo[am][1] = __float_as_uint(Asl[(ks + tig) * AS_STRIDE + mb + g + 8]);
                alo[am][2] = __float_as_uint(Asl[(ks + tig + 4) * AS_STRIDE + mb + g]);
                alo[am][3] = __float_as_uint(Asl[(ks + tig + 4) * AS_STRIDE + mb + g + 8]);
            }
            #pragma unroll
            for (int an = 0; an < 4; an++) {
                const int nb = wn * 32 + an * 8;
                bhi[an][0] = __float_as_uint(Bsh[(ks + tig) * BS_STRIDE + nb + g]);
                bhi[an][1] = __float_as_uint(Bsh[(ks + tig + 4) * BS_STRIDE + nb + g]);
                blo[an][0] = __float_as_uint(Bsl[(ks + tig) * BS_STRIDE + nb + g]);
                blo[an][1] = __float_as_uint(Bsl[(ks + tig + 4) * BS_STRIDE + nb + g]);
            }
            #pragma unroll
            for (int am = 0; am < 2; am++)
                #pragma unroll
                for (int an = 0; an < 4; an++) {
                    mma_tf32(c[am][an], ahi[am][0], ahi[am][1], ahi[am][2], ahi[am][3],
                             bhi[an][0], bhi[an][1]);
                    mma_tf32(c[am][an], ahi[am][0], ahi[am][1], ahi[am][2], ahi[am][3],
                             blo[an][0], blo[an][1]);
                    mma_tf32(c[am][an], alo[am][0], alo[am][1], alo[am][2], alo[am][3],
                             bhi[an][0], bhi[an][1]);
                }
        }
        __syncthreads();
    }

    #pragma unroll
    for (int an = 0; an < 4; an++) {
        const int o = bn + wn * 32 + an * 8 + 2 * tig;
        const float2 b2 = *(const float2*)&bias[o];
        const int which = o >> 8;
        const int cc = o & 255;
        const int h = cc >> 5;
        const int d0 = cc & 31;
        float* dst = (which == 0) ? g_k : (which == 1) ? g_q : g_v;
        #pragma unroll
        for (int am = 0; am < 2; am++) {
            const int r0 = wm * 32 + am * 16 + g;
            const int t1 = t0 + r0;
            const int t2 = t1 + 8;
            float2 lo = make_float2(c[am][an][0] + b2.x, c[am][an][1] + b2.y);
            float2 hi = make_float2(c[am][an][2] + b2.x, c[am][an][3] + b2.y);
            *(float2*)&dst[((size_t)(n * NHEAD + h) * TSEQ + t1) * HDIM + d0] = lo;
            *(float2*)&dst[((size_t)(n * NHEAD + h) * TSEQ + t2) * HDIM + d0] = hi;
        }
    }
}

// ---------------------------------------------------------------------------
// Kernel 2a: split-K causal flash attention (partials). R9-proven.
// ---------------------------------------------------------------------------
__global__ __launch_bounds__(128) void attn_partial() {
    int x = blockIdx.x;
    int qt = 0, base = 0;
    while (x >= base + qt + 1) { base += qt + 1; qt++; }
    const int p = x - base;
    const int nh = blockIdx.y;
    const int tid = threadIdx.x;
    const int tq = qt * 128 + tid;

    const float* Qb = g_q + (size_t)nh * TSEQ * HDIM;
    const float* Kb = g_k + (size_t)nh * TSEQ * HDIM;
    const float* Vb = g_v + (size_t)nh * TSEQ * HDIM;

    u64 q2[16];
    {
        const u64 sc2 = bcast2(0.17677669529663687f);
        const u64* qsrc = (const u64*)(Qb + (size_t)tq * HDIM);
        #pragma unroll
        for (int d2 = 0; d2 < 16; d2++) q2[d2] = mul2(qsrc[d2], sc2);
    }

    u64 acc[16];
    #pragma unroll
    for (int d2 = 0; d2 < 16; d2++) acc[d2] = 0ull;
    float lsum = 0.0f;

    __shared__ float Ks[128 * 32];
    __shared__ float Vs[128 * 32];

    {
        const float4* ksrc = (const float4*)(Kb + (size_t)p * 128 * HDIM);
        const float4* vsrc = (const float4*)(Vb + (size_t)p * 128 * HDIM);
        #pragma unroll
        for (int l = 0; l < 8; l++) {
            ((float4*)Ks)[l * 128 + tid] = ksrc[l * 128 + tid];
            ((float4*)Vs)[l * 128 + tid] = vsrc[l * 128 + tid];
        }
    }
    __syncthreads();

    const bool diag = (p == qt);

    for (int c = 0; c < 8; c++) {
        float pr[16];
        #pragma unroll
        for (int j = 0; j < 16; j++) {
            const int key = c * 16 + j;
            const float4* kp4 = (const float4*)&Ks[key * 32];
            u64 s0 = 0ull, s1 = 0ull, s2 = 0ull, s3 = 0ull;
            #pragma unroll
            for (int q = 0; q < 4; q++) {
                float4 ka = kp4[q * 2 + 0];
                float4 kb = kp4[q * 2 + 1];
                const u64* kap = (const u64*)&ka;
                const u64* kbp = (const u64*)&kb;
                s0 = fma2(q2[q * 4 + 0], kap[0], s0);
                s1 = fma2(q2[q * 4 + 1], kap[1], s1);
                s2 = fma2(q2[q * 4 + 2], kbp[0], s2);
                s3 = fma2(q2[q * 4 + 3], kbp[1], s3);
            }
            float2 sf = unpk2(add2(add2(s0, s1), add2(s2, s3)));
            float pe = __expf(sf.x + sf.y);
            if (diag && key > tid) pe = 0.0f;
            pr[j] = pe;
        }
        #pragma unroll
        for (int j = 0; j < 16; j++) {
            lsum += pr[j];
            const u64 pd = bcast2(pr[j]);
            const float4* vp4 = (const float4*)&Vs[(c * 16 + j) * 32];
            #pragma unroll
            for (int q = 0; q < 4; q++) {
                float4 va = vp4[q * 2 + 0];
                float4 vb = vp4[q * 2 + 1];
                const u64* vap = (const u64*)&va;
                const u64* vbp = (const u64*)&vb;
                acc[q * 4 + 0] = fma2(pd, vap[0], acc[q * 4 + 0]);
                acc[q * 4 + 1] = fma2(pd, vap[1], acc[q * 4 + 1]);
                acc[q * 4 + 2] = fma2(pd, vbp[0], acc[q * 4 + 2]);
                acc[q * 4 + 3] = fma2(pd, vbp[1], acc[q * 4 + 3]);
            }
        }
    }

    float* pout = g_pacc + ((size_t)(nh * 36 + x) * 32) * 128;
    #pragma unroll
    for (int d2 = 0; d2 < 16; d2++) {
        float2 f = unpk2(acc[d2]);
        pout[(2 * d2 + 0) * 128 + tid] = f.x;
        pout[(2 * d2 + 1) * 128 + tid] = f.y;
    }
    g_plsum[(size_t)(nh * 36 + x) * 128 + tid] = lsum;
}

// ---------------------------------------------------------------------------
// Kernel 2b: reduce partials -> g_attn_hi/lo [C, N*T] (pre-split for mix).
// ---------------------------------------------------------------------------
__global__ __launch_bounds__(128) void attn_reduce() {
    const int qt = blockIdx.x;
    const int nh = blockIdx.y;
    const int tid = threadIdx.x;
    const int tq = qt * 128 + tid;
    const int base = qt * (qt + 1) / 2;

    float acc[32];
    #pragma unroll
    for (int d = 0; d < 32; d++) acc[d] = 0.0f;
    float lsum = 0.0f;

    for (int p = 0; p <= qt; p++) {
        const float* pin = g_pacc + ((size_t)(nh * 36 + base + p) * 32) * 128;
        #pragma unroll
        for (int d = 0; d < 32; d++) acc[d] += pin[d * 128 + tid];
        lsum += g_plsum[(size_t)(nh * 36 + base + p) * 128 + tid];
    }

    const float inv = 1.0f / lsum;
    const int n = nh >> 3;
    const int h = nh & 7;
    const size_t mcol = (size_t)n * TSEQ + tq;
    #pragma unroll
    for (int d = 0; d < 32; d++) {
        float v = acc[d] * inv;
        unsigned hh, ll;
        tf32_split(v, hh, ll);
        const size_t gi = (size_t)(h * HDIM + d) * (NBATCH * TSEQ) + mcol;
        g_attn_hi[gi] = __uint_as_float(hh);
        g_attn_lo[gi] = __uint_as_float(ll);
    }
}

// ---------------------------------------------------------------------------
// Kernel 3: mix + bias + residual via 3xTF32 mma.sync, pre-split operands.
// ---------------------------------------------------------------------------
__global__ __launch_bounds__(256) void mix_mma(const float* __restrict__ image,
                                               const float* __restrict__ bias,
                                               float* __restrict__ out) {
    __shared__ float Ash[16 * AS_STRIDE];
    __shared__ float Asl[16 * AS_STRIDE];
    __shared__ float Bsh[16 * BS_STRIDE];
    __shared__ float Bsl[16 * BS_STRIDE];
    const int tid = threadIdx.x;
    const int lane = tid & 31;
    const int wid = tid >> 5;
    const int wm = wid & 3;
    const int wn = wid >> 2;
    const int g = lane >> 2, tig = lane & 3;
    const int bm = blockIdx.y * 128;
    const int bn = blockIdx.x * 64;
    const int n  = bm >> 10;
    const int t0 = bm & 1023;

    float c[2][4][4];
    #pragma unroll
    for (int am = 0; am < 2; am++)
        #pragma unroll
        for (int an = 0; an < 4; an++)
            #pragma unroll
            for (int i = 0; i < 4; i++) c[am][an][i] = 0.0f;

    float4 pah[2], pal[2], pbh, pbl;
    {
        #pragma unroll
        for (int l = 0; l < 2; l++) {
            int idx = l * 256 + tid;
            int k = idx >> 5, f = idx & 31;
            pah[l] = *(const float4*)&g_attn_hi[(size_t)k * 8192 + bm + f * 4];
            pal[l] = *(const float4*)&g_attn_lo[(size_t)k * 8192 + bm + f * 4];
        }
        int k = tid >> 4, f = tid & 15;
        pbh = *(const float4*)&g_wm_hi[k * 256 + bn + f * 4];
        pbl = *(const float4*)&g_wm_lo[k * 256 + bn + f * 4];
    }

    for (int k0 = 0; k0 < 256; k0 += 16) {
        #pragma unroll
        for (int l = 0; l < 2; l++) {
            int idx = l * 256 + tid;
            int k = idx >> 5, f = idx & 31;
            *(float4*)&Ash[k * AS_STRIDE + f * 4] = pah[l];
            *(float4*)&Asl[k * AS_STRIDE + f * 4] = pal[l];
        }
        {
            int k = tid >> 4, f = tid & 15;
            *(float4*)&Bsh[k * BS_STRIDE + f * 4] = pbh;
            *(float4*)&Bsl[k * BS_STRIDE + f * 4] = pbl;
        }
        __syncthreads();
        if (k0 + 16 < 256) {
            #pragma unroll
            for (int l = 0; l < 2; l++) {
                int idx = l * 256 + tid;
                int k = idx >> 5, f = idx & 31;
                pah[l] = *(const float4*)&g_attn_hi[(size_t)(k0 + 16 + k) * 8192 + bm + f * 4];
                pal[l] = *(const float4*)&g_attn_lo[(size_t)(k0 + 16 + k) * 8192 + bm + f * 4];
            }
            int k = tid >> 4, f = tid & 15;
            pbh = *(const float4*)&g_wm_hi[(k0 + 16 + k) * 256 + bn + f * 4];
            pbl = *(const float4*)&g_wm_lo[(k0 + 16 + k) * 256 + bn + f * 4];
        }
        #pragma unroll
        for (int ks = 0; ks < 16; ks += 8) {
            unsigned ahi[2][4], alo[2][4], bhi[4][2], blo[4][2];
            #pragma unroll
            for (int am = 0; am < 2; am++) {
                const int mb = wm * 32 + am * 16;
                ahi[am][0] = __float_as_uint(Ash[(ks + tig) * AS_STRIDE + mb + g]);
                ahi[am][1] = __float_as_uint(Ash[(ks + tig) * AS_STRIDE + mb + g + 8]);
                ahi[am][2] = __float_as_uint(Ash[(ks + tig + 4) * AS_STRIDE + mb + g]);
                ahi[am][3] = __float_as_uint(Ash[(ks + tig + 4) * AS_STRIDE + mb + g + 8]);
                alo[am][0] = __float_as_uint(Asl[(ks + tig) * AS_STRIDE + mb + g]);
                alo[am][1] = __float_as_uint(Asl[(ks + tig) * AS_STRIDE + mb + g + 8]);
                alo[am][2] = __float_as_uint(Asl[(ks + tig + 4) * AS_STRIDE + mb + g]);
                alo[am][3] = __float_as_uint(Asl[(ks + tig + 4) * AS_STRIDE + mb + g + 8]);
            }
            #pragma unroll
            for (int an = 0; an < 4; an++) {
                const int nb = wn * 32 + an * 8;
                bhi[an][0] = __float_as_uint(Bsh[(ks + tig) * BS_STRIDE + nb + g]);
                bhi[an][1] = __float_as_uint(Bsh[(ks + tig + 4) * BS_STRIDE + nb + g]);
                blo[an][0] = __float_as_uint(Bsl[(ks + tig) * BS_STRIDE + nb + g]);
                blo[an][1] = __float_as_uint(Bsl[(ks + tig + 4) * BS_STRIDE + nb + g]);
            }
            #pragma unroll
            for (int am = 0; am < 2; am++)
                #pragma unroll
                for (int an = 0; an < 4; an++) {
                    mma_tf32(c[am][an], ahi[am][0], ahi[am][1], ahi[am][2], ahi[am][3],
                             bhi[an][0], bhi[an][1]);
                    mma_tf32(c[am][an], ahi[am][0], ahi[am][1], ahi[am][2], ahi[am][3],
                             blo[an][0], blo[an][1]);
                    mma_tf32(c[am][an], alo[am][0], alo[am][1], alo[am][2], alo[am][3],
                             bhi[an][0], bhi[an][1]);
                }
        }
        __syncthreads();
    }

    #pragma unroll
    for (int an = 0; an < 4; an++) {
        const int o = bn + wn * 32 + an * 8 + 2 * tig;
        const float2 b2 = *(const float2*)&bias[o];
        #pragma unroll
        for (int am = 0; am < 2; am++) {
            const int r0 = wm * 32 + am * 16 + g;
            const int t1 = t0 + r0;
            const size_t g00 = (size_t)n * 262144 + (size_t)o * 1024 + t1;
            const size_t g01 = g00 + 1024;
            out[g00]     = c[am][an][0] + b2.x + image[g00];
            out[g01]     = c[am][an][1] + b2.y + image[g01];
            out[g00 + 8] = c[am][an][2] + b2.x + image[g00 + 8];
            out[g01 + 8] = c[am][an][3] + b2.y + image[g01 + 8];
        }
    }
}

// ---------------------------------------------------------------------------
extern "C" void kernel_launch(void* const* d_in, const int* in_sizes, int n_in,
                              void* d_out, int out_size) {
    const float* image = (const float*)d_in[0];
    const float* w_kqv = (const float*)d_in[1];
    const float* b_kqv = (const float*)d_in[2];
    const float* w_mix = (const float*)d_in[3];
    const float* b_mix = (const float*)d_in[4];
    float* out = (float*)d_out;

    presplit<<<2304, 256>>>(image, w_kqv, w_mix);

    dim3 gridA(768 / 64, 8192 / 128);
    kqv_mma<<<gridA, 256>>>(b_kqv);

    dim3 gridB(36, 64);
    attn_partial<<<gridB, 128>>>();

    dim3 gridR(8, 64);
    attn_reduce<<<gridR, 128>>>();

    dim3 gridC(256 / 64, 8192 / 128);
    mix_mma<<<gridC, 256>>>(image, b_mix, out);
}

// round 11
// speedup vs baseline: 1.0675x; 1.0675x over previous
#include <cuda_runtime.h>
#include <math.h>

// Problem constants
#define NBATCH 8
#define CCH    256
#define TSEQ   1024
#define NHEAD  8
#define HDIM   32

typedef unsigned long long u64;

// ---- packed f32x2 primitives (sm_100+) ----
__device__ __forceinline__ u64 bcast2(float x) {
    u64 r; asm("mov.b64 %0, {%1, %1};" : "=l"(r) : "f"(x)); return r;
}
__device__ __forceinline__ u64 fma2(u64 a, u64 b, u64 c) {
    u64 d; asm("fma.rn.f32x2 %0, %1, %2, %3;" : "=l"(d) : "l"(a), "l"(b), "l"(c));
    return d;
}
__device__ __forceinline__ u64 mul2(u64 a, u64 b) {
    u64 d; asm("mul.rn.f32x2 %0, %1, %2;" : "=l"(d) : "l"(a), "l"(b)); return d;
}
__device__ __forceinline__ u64 add2(u64 a, u64 b) {
    u64 d; asm("add.rn.f32x2 %0, %1, %2;" : "=l"(d) : "l"(a), "l"(b)); return d;
}
__device__ __forceinline__ float2 unpk2(u64 a) {
    float2 f; asm("mov.b64 {%0, %1}, %2;" : "=f"(f.x), "=f"(f.y) : "l"(a)); return f;
}

// ---- tf32 mma primitives ----
__device__ __forceinline__ unsigned tf32_of(float x) {
    unsigned r; asm("cvt.rna.tf32.f32 %0, %1;" : "=r"(r) : "f"(x)); return r;
}
__device__ __forceinline__ void tf32_split(float v, unsigned& hi, unsigned& lo) {
    hi = tf32_of(v);
    lo = tf32_of(v - __uint_as_float(hi));
}
__device__ __forceinline__ void mma_tf32(float c[4],
                                         unsigned a0, unsigned a1, unsigned a2, unsigned a3,
                                         unsigned b0, unsigned b1) {
    asm("mma.sync.aligned.m16n8k8.row.col.f32.tf32.tf32.f32 "
        "{%0,%1,%2,%3}, {%4,%5,%6,%7}, {%8,%9}, {%0,%1,%2,%3};"
        : "+f"(c[0]), "+f"(c[1]), "+f"(c[2]), "+f"(c[3])
        : "r"(a0), "r"(a1), "r"(a2), "r"(a3), "r"(b0), "r"(b1));
}

// Scratch. K/Q/V in [N, H, T, D]. g_attn TRANSPOSED: [C, N*T].
__device__ float g_k[NBATCH * NHEAD * TSEQ * HDIM];
__device__ float g_q[NBATCH * NHEAD * TSEQ * HDIM];
__device__ float g_v[NBATCH * NHEAD * TSEQ * HDIM];
__device__ float g_attn[CCH * NBATCH * TSEQ];
// Split-K partials: 36 = sum_{qt}(qt+1) work units per nh.
__device__ float g_pacc[64 * 36 * 32 * 128];
__device__ float g_plsum[64 * 36 * 128];
__device__ float g_inv[64 * 8 * 128];     // 1/lsum per (nh, qt, q)

#define AS_STRIDE 136
#define BS_STRIDE 72

// ---------------------------------------------------------------------------
// Kernel 1: KQV projection via 3xTF32 mma.sync (R7/R8/R9-proven).
// ---------------------------------------------------------------------------
__global__ __launch_bounds__(256) void kqv_mma(const float* __restrict__ image,
                                               const float* __restrict__ w,
                                               const float* __restrict__ bias) {
    __shared__ float As[16 * AS_STRIDE];
    __shared__ float Bs[16 * BS_STRIDE];
    const int tid = threadIdx.x;
    const int lane = tid & 31;
    const int wid = tid >> 5;
    const int wm = wid & 3;
    const int wn = wid >> 2;
    const int g = lane >> 2, tig = lane & 3;
    const int bm = blockIdx.y * 128;
    const int bn = blockIdx.x * 64;
    const int n  = bm >> 10;
    const int t0 = bm & 1023;

    float c[2][4][4];
    #pragma unroll
    for (int am = 0; am < 2; am++)
        #pragma unroll
        for (int an = 0; an < 4; an++)
            #pragma unroll
            for (int i = 0; i < 4; i++) c[am][an][i] = 0.0f;

    float4 pa[2], pb;
    {
        #pragma unroll
        for (int l = 0; l < 2; l++) {
            int idx = l * 256 + tid;
            int k = idx >> 5, f = idx & 31;
            pa[l] = *(const float4*)&image[n * 262144 + k * 1024 + t0 + f * 4];
        }
        int k = tid >> 4, f = tid & 15;
        pb = *(const float4*)&w[k * 768 + bn + f * 4];
    }

    for (int k0 = 0; k0 < 256; k0 += 16) {
        #pragma unroll
        for (int l = 0; l < 2; l++) {
            int idx = l * 256 + tid;
            int k = idx >> 5, f = idx & 31;
            *(float4*)&As[k * AS_STRIDE + f * 4] = pa[l];
        }
        {
            int k = tid >> 4, f = tid & 15;
            *(float4*)&Bs[k * BS_STRIDE + f * 4] = pb;
        }
        __syncthreads();
        if (k0 + 16 < 256) {
            #pragma unroll
            for (int l = 0; l < 2; l++) {
                int idx = l * 256 + tid;
                int k = idx >> 5, f = idx & 31;
                pa[l] = *(const float4*)&image[n * 262144 + (k0 + 16 + k) * 1024 + t0 + f * 4];
            }
            int k = tid >> 4, f = tid & 15;
            pb = *(const float4*)&w[(k0 + 16 + k) * 768 + bn + f * 4];
        }
        #pragma unroll
        for (int ks = 0; ks < 16; ks += 8) {
            unsigned ahi[2][4], alo[2][4], bhi[4][2], blo[4][2];
            #pragma unroll
            for (int am = 0; am < 2; am++) {
                const int mbase = wm * 32 + am * 16;
                float v0 = As[(ks + tig) * AS_STRIDE + mbase + g];
                float v1 = As[(ks + tig) * AS_STRIDE + mbase + g + 8];
                float v2 = As[(ks + tig + 4) * AS_STRIDE + mbase + g];
                float v3 = As[(ks + tig + 4) * AS_STRIDE + mbase + g + 8];
                tf32_split(v0, ahi[am][0], alo[am][0]);
                tf32_split(v1, ahi[am][1], alo[am][1]);
                tf32_split(v2, ahi[am][2], alo[am][2]);
                tf32_split(v3, ahi[am][3], alo[am][3]);
            }
            #pragma unroll
            for (int an = 0; an < 4; an++) {
                const int nbase = wn * 32 + an * 8;
                float u0 = Bs[(ks + tig) * BS_STRIDE + nbase + g];
                float u1 = Bs[(ks + tig + 4) * BS_STRIDE + nbase + g];
                tf32_split(u0, bhi[an][0], blo[an][0]);
                tf32_split(u1, bhi[an][1], blo[an][1]);
            }
            #pragma unroll
            for (int am = 0; am < 2; am++)
                #pragma unroll
                for (int an = 0; an < 4; an++) {
                    mma_tf32(c[am][an], ahi[am][0], ahi[am][1], ahi[am][2], ahi[am][3],
                             bhi[an][0], bhi[an][1]);
                    mma_tf32(c[am][an], ahi[am][0], ahi[am][1], ahi[am][2], ahi[am][3],
                             blo[an][0], blo[an][1]);
                    mma_tf32(c[am][an], alo[am][0], alo[am][1], alo[am][2], alo[am][3],
                             bhi[an][0], bhi[an][1]);
                }
        }
        __syncthreads();
    }

    #pragma unroll
    for (int an = 0; an < 4; an++) {
        const int o = bn + wn * 32 + an * 8 + 2 * tig;
        const float2 b2 = *(const float2*)&bias[o];
        const int which = o >> 8;
        const int cc = o & 255;
        const int h = cc >> 5;
        const int d0 = cc & 31;
        float* dst = (which == 0) ? g_k : (which == 1) ? g_q : g_v;
        #pragma unroll
        for (int am = 0; am < 2; am++) {
            const int r0 = wm * 32 + am * 16 + g;
            const int t1 = t0 + r0;
            const int t2 = t1 + 8;
            float2 lo = make_float2(c[am][an][0] + b2.x, c[am][an][1] + b2.y);
            float2 hi = make_float2(c[am][an][2] + b2.x, c[am][an][3] + b2.y);
            *(float2*)&dst[((size_t)(n * NHEAD + h) * TSEQ + t1) * HDIM + d0] = lo;
            *(float2*)&dst[((size_t)(n * NHEAD + h) * TSEQ + t2) * HDIM + d0] = hi;
        }
    }
}

// ---------------------------------------------------------------------------
// Kernel 2a: split-K causal flash attention (partials). R9-proven.
// ---------------------------------------------------------------------------
__global__ __launch_bounds__(128) void attn_partial() {
    int x = blockIdx.x;
    int qt = 0, base = 0;
    while (x >= base + qt + 1) { base += qt + 1; qt++; }
    const int p = x - base;
    const int nh = blockIdx.y;
    const int tid = threadIdx.x;
    const int tq = qt * 128 + tid;

    const float* Qb = g_q + (size_t)nh * TSEQ * HDIM;
    const float* Kb = g_k + (size_t)nh * TSEQ * HDIM;
    const float* Vb = g_v + (size_t)nh * TSEQ * HDIM;

    u64 q2[16];
    {
        const u64 sc2 = bcast2(0.17677669529663687f);
        const u64* qsrc = (const u64*)(Qb + (size_t)tq * HDIM);
        #pragma unroll
        for (int d2 = 0; d2 < 16; d2++) q2[d2] = mul2(qsrc[d2], sc2);
    }

    u64 acc[16];
    #pragma unroll
    for (int d2 = 0; d2 < 16; d2++) acc[d2] = 0ull;
    float lsum = 0.0f;

    __shared__ float Ks[128 * 32];
    __shared__ float Vs[128 * 32];

    {
        const float4* ksrc = (const float4*)(Kb + (size_t)p * 128 * HDIM);
        const float4* vsrc = (const float4*)(Vb + (size_t)p * 128 * HDIM);
        #pragma unroll
        for (int l = 0; l < 8; l++) {
            ((float4*)Ks)[l * 128 + tid] = ksrc[l * 128 + tid];
            ((float4*)Vs)[l * 128 + tid] = vsrc[l * 128 + tid];
        }
    }
    __syncthreads();

    const bool diag = (p == qt);

    for (int c = 0; c < 8; c++) {
        float pr[16];
        #pragma unroll
        for (int j = 0; j < 16; j++) {
            const int key = c * 16 + j;
            const float4* kp4 = (const float4*)&Ks[key * 32];
            u64 s0 = 0ull, s1 = 0ull, s2 = 0ull, s3 = 0ull;
            #pragma unroll
            for (int q = 0; q < 4; q++) {
                float4 ka = kp4[q * 2 + 0];
                float4 kb = kp4[q * 2 + 1];
                const u64* kap = (const u64*)&ka;
                const u64* kbp = (const u64*)&kb;
                s0 = fma2(q2[q * 4 + 0], kap[0], s0);
                s1 = fma2(q2[q * 4 + 1], kap[1], s1);
                s2 = fma2(q2[q * 4 + 2], kbp[0], s2);
                s3 = fma2(q2[q * 4 + 3], kbp[1], s3);
            }
            float2 sf = unpk2(add2(add2(s0, s1), add2(s2, s3)));
            float pe = __expf(sf.x + sf.y);
            if (diag && key > tid) pe = 0.0f;
            pr[j] = pe;
        }
        #pragma unroll
        for (int j = 0; j < 16; j++) {
            lsum += pr[j];
            const u64 pd = bcast2(pr[j]);
            const float4* vp4 = (const float4*)&Vs[(c * 16 + j) * 32];
            #pragma unroll
            for (int q = 0; q < 4; q++) {
                float4 va = vp4[q * 2 + 0];
                float4 vb = vp4[q * 2 + 1];
                const u64* vap = (const u64*)&va;
                const u64* vbp = (const u64*)&vb;
                acc[q * 4 + 0] = fma2(pd, vap[0], acc[q * 4 + 0]);
                acc[q * 4 + 1] = fma2(pd, vap[1], acc[q * 4 + 1]);
                acc[q * 4 + 2] = fma2(pd, vbp[0], acc[q * 4 + 2]);
                acc[q * 4 + 3] = fma2(pd, vbp[1], acc[q * 4 + 3]);
            }
        }
    }

    float* pout = g_pacc + ((size_t)(nh * 36 + x) * 32) * 128;
    #pragma unroll
    for (int d2 = 0; d2 < 16; d2++) {
        float2 f = unpk2(acc[d2]);
        pout[(2 * d2 + 0) * 128 + tid] = f.x;
        pout[(2 * d2 + 1) * 128 + tid] = f.y;
    }
    g_plsum[(size_t)(nh * 36 + x) * 128 + tid] = lsum;
}

// ---------------------------------------------------------------------------
// Kernel 2b: per-query inverse lsum. 65536 threads: (nh, qt, q).
// ---------------------------------------------------------------------------
__global__ __launch_bounds__(256) void attn_inv() {
    const int t = blockIdx.x * 256 + threadIdx.x;   // 65536 total
    const int q  = t & 127;
    const int qt = (t >> 7) & 7;
    const int nh = t >> 10;
    const int base = qt * (qt + 1) / 2;

    float lsum = 0.0f;
    for (int p = 0; p <= qt; p++)
        lsum += g_plsum[(size_t)(nh * 36 + base + p) * 128 + q];
    g_inv[t] = 1.0f / lsum;
}

// ---------------------------------------------------------------------------
// Kernel 2c: element-parallel reduce -> g_attn [C, N*T].
// One thread per output element: 2.1M threads (8192 blocks x 256).
// Coalesced L2-resident reads, full MLP, deterministic order (p ascending).
// ---------------------------------------------------------------------------
__global__ __launch_bounds__(256) void attn_reduce2() {
    const int t = blockIdx.x * 256 + threadIdx.x;   // 2097152 total
    const int q  = t & 127;
    const int d  = (t >> 7) & 31;
    const int qt = (t >> 12) & 7;
    const int nh = t >> 15;
    const int base = qt * (qt + 1) / 2;

    float acc = 0.0f;
    const float* pin = g_pacc + ((size_t)(nh * 36 + base) * 32 + d) * 128 + q;
    #pragma unroll 4
    for (int p = 0; p <= qt; p++)
        acc += pin[(size_t)p * 32 * 128];

    const float inv = g_inv[(nh * 8 + qt) * 128 + q];
    const int n = nh >> 3;
    const int h = nh & 7;
    const int tq = qt * 128 + q;
    g_attn[(size_t)(h * HDIM + d) * (NBATCH * TSEQ) + (size_t)n * TSEQ + tq] = acc * inv;
}

// ---------------------------------------------------------------------------
// Kernel 3: mix + bias + residual via 3xTF32 mma.sync (R9-proven).
// ---------------------------------------------------------------------------
__global__ __launch_bounds__(256) void mix_mma(const float* __restrict__ image,
                                               const float* __restrict__ w,
                                               const float* __restrict__ bias,
                                               float* __restrict__ out) {
    __shared__ float As[16 * AS_STRIDE];
    __shared__ float Bs[16 * BS_STRIDE];
    const int tid = threadIdx.x;
    const int lane = tid & 31;
    const int wid = tid >> 5;
    const int wm = wid & 3;
    const int wn = wid >> 2;
    const int g = lane >> 2, tig = lane & 3;
    const int bm = blockIdx.y * 128;
    const int bn = blockIdx.x * 64;
    const int n  = bm >> 10;
    const int t0 = bm & 1023;

    float c[2][4][4];
    #pragma unroll
    for (int am = 0; am < 2; am++)
        #pragma unroll
        for (int an = 0; an < 4; an++)
            #pragma unroll
            for (int i = 0; i < 4; i++) c[am][an][i] = 0.0f;

    float4 pa[2], pb;
    {
        #pragma unroll
        for (int l = 0; l < 2; l++) {
            int idx = l * 256 + tid;
            int k = idx >> 5, f = idx & 31;
            pa[l] = *(const float4*)&g_attn[(size_t)k * 8192 + bm + f * 4];
        }
        int k = tid >> 4, f = tid & 15;
        pb = *(const float4*)&w[k * 256 + bn + f * 4];
    }

    for (int k0 = 0; k0 < 256; k0 += 16) {
        #pragma unroll
        for (int l = 0; l < 2; l++) {
            int idx = l * 256 + tid;
            int k = idx >> 5, f = idx & 31;
            *(float4*)&As[k * AS_STRIDE + f * 4] = pa[l];
        }
        {
            int k = tid >> 4, f = tid & 15;
            *(float4*)&Bs[k * BS_STRIDE + f * 4] = pb;
        }
        __syncthreads();
        if (k0 + 16 < 256) {
            #pragma unroll
            for (int l = 0; l < 2; l++) {
                int idx = l * 256 + tid;
                int k = idx >> 5, f = idx & 31;
                pa[l] = *(const float4*)&g_attn[(size_t)(k0 + 16 + k) * 8192 + bm + f * 4];
            }
            int k = tid >> 4, f = tid & 15;
            pb = *(const float4*)&w[(k0 + 16 + k) * 256 + bn + f * 4];
        }
        #pragma unroll
        for (int ks = 0; ks < 16; ks += 8) {
            unsigned ahi[2][4], alo[2][4], bhi[4][2], blo[4][2];
            #pragma unroll
            for (int am = 0; am < 2; am++) {
                const int mbase = wm * 32 + am * 16;
                float v0 = As[(ks + tig) * AS_STRIDE + mbase + g];
                float v1 = As[(ks + tig) * AS_STRIDE + mbase + g + 8];
                float v2 = As[(ks + tig + 4) * AS_STRIDE + mbase + g];
                float v3 = As[(ks + tig + 4) * AS_STRIDE + mbase + g + 8];
                tf32_split(v0, ahi[am][0], alo[am][0]);
                tf32_split(v1, ahi[am][1], alo[am][1]);
                tf32_split(v2, ahi[am][2], alo[am][2]);
                tf32_split(v3, ahi[am][3], alo[am][3]);
            }
            #pragma unroll
            for (int an = 0; an < 4; an++) {
                const int nbase = wn * 32 + an * 8;
                float u0 = Bs[(ks + tig) * BS_STRIDE + nbase + g];
                float u1 = Bs[(ks + tig + 4) * BS_STRIDE + nbase + g];
                tf32_split(u0, bhi[an][0], blo[an][0]);
                tf32_split(u1, bhi[an][1], blo[an][1]);
            }
            #pragma unroll
            for (int am = 0; am < 2; am++)
                #pragma unroll
                for (int an = 0; an < 4; an++) {
                    mma_tf32(c[am][an], ahi[am][0], ahi[am][1], ahi[am][2], ahi[am][3],
                             bhi[an][0], bhi[an][1]);
                    mma_tf32(c[am][an], ahi[am][0], ahi[am][1], ahi[am][2], ahi[am][3],
                             blo[an][0], blo[an][1]);
                    mma_tf32(c[am][an], alo[am][0], alo[am][1], alo[am][2], alo[am][3],
                             bhi[an][0], bhi[an][1]);
                }
        }
        __syncthreads();
    }

    #pragma unroll
    for (int an = 0; an < 4; an++) {
        const int o = bn + wn * 32 + an * 8 + 2 * tig;
        const float2 b2 = *(const float2*)&bias[o];
        #pragma unroll
        for (int am = 0; am < 2; am++) {
            const int r0 = wm * 32 + am * 16 + g;
            const int t1 = t0 + r0;
            const size_t g00 = (size_t)n * 262144 + (size_t)o * 1024 + t1;
            const size_t g01 = g00 + 1024;
            out[g00]     = c[am][an][0] + b2.x + image[g00];
            out[g01]     = c[am][an][1] + b2.y + image[g01];
            out[g00 + 8] = c[am][an][2] + b2.x + image[g00 + 8];
            out[g01 + 8] = c[am][an][3] + b2.y + image[g01 + 8];
        }
    }
}

// ---------------------------------------------------------------------------
extern "C" void kernel_launch(void* const* d_in, const int* in_sizes, int n_in,
                              void* d_out, int out_size) {
    const float* image = (const float*)d_in[0];
    const float* w_kqv = (const float*)d_in[1];
    const float* b_kqv = (const float*)d_in[2];
    const float* w_mix = (const float*)d_in[3];
    const float* b_mix = (const float*)d_in[4];
    float* out = (float*)d_out;

    dim3 gridA(768 / 64, 8192 / 128);
    kqv_mma<<<gridA, 256>>>(image, w_kqv, b_kqv);

    dim3 gridB(36, 64);
    attn_partial<<<gridB, 128>>>();

    attn_inv<<<256, 256>>>();
    attn_reduce2<<<8192, 256>>>();

    dim3 gridC(256 / 64, 8192 / 128);
    mix_mma<<<gridC, 256>>>(image, w_mix, b_mix, out);
}

// round 12
// speedup vs baseline: 1.1117x; 1.0414x over previous
#include <cuda_runtime.h>
#include <math.h>

// Problem constants
#define NBATCH 8
#define CCH    256
#define TSEQ   1024
#define NHEAD  8
#define HDIM   32

// ---- tf32 mma primitives ----
__device__ __forceinline__ unsigned tf32_of(float x) {
    unsigned r; asm("cvt.rna.tf32.f32 %0, %1;" : "=r"(r) : "f"(x)); return r;
}
__device__ __forceinline__ void tf32_split(float v, unsigned& hi, unsigned& lo) {
    hi = tf32_of(v);
    lo = tf32_of(v - __uint_as_float(hi));
}
__device__ __forceinline__ void mma_tf32(float c[4],
                                         unsigned a0, unsigned a1, unsigned a2, unsigned a3,
                                         unsigned b0, unsigned b1) {
    asm("mma.sync.aligned.m16n8k8.row.col.f32.tf32.tf32.f32 "
        "{%0,%1,%2,%3}, {%4,%5,%6,%7}, {%8,%9}, {%0,%1,%2,%3};"
        : "+f"(c[0]), "+f"(c[1]), "+f"(c[2]), "+f"(c[3])
        : "r"(a0), "r"(a1), "r"(a2), "r"(a3), "r"(b0), "r"(b1));
}

// Scratch. K/Q/V in [N, H, T, D]. g_attn TRANSPOSED: [C, N*T].
__device__ float g_k[NBATCH * NHEAD * TSEQ * HDIM];
__device__ float g_q[NBATCH * NHEAD * TSEQ * HDIM];
__device__ float g_v[NBATCH * NHEAD * TSEQ * HDIM];
__device__ float g_attn[CCH * NBATCH * TSEQ];
// Split-K partials: 72 units/nh of 64 queries x 128 keys.
__device__ float g_pacc[64 * 72 * 32 * 64];
__device__ float g_plsum[64 * 72 * 64];
__device__ float g_inv[64 * 16 * 64];     // 1/lsum per (nh, qt2, q)

#define AS_STRIDE 136
#define BS_STRIDE 72

// ---------------------------------------------------------------------------
// Kernel 1: KQV projection via 3xTF32 mma.sync (R7-R11 proven).
// ---------------------------------------------------------------------------
__global__ __launch_bounds__(256) void kqv_mma(const float* __restrict__ image,
                                               const float* __restrict__ w,
                                               const float* __restrict__ bias) {
    __shared__ float As[16 * AS_STRIDE];
    __shared__ float Bs[16 * BS_STRIDE];
    const int tid = threadIdx.x;
    const int lane = tid & 31;
    const int wid = tid >> 5;
    const int wm = wid & 3;
    const int wn = wid >> 2;
    const int g = lane >> 2, tig = lane & 3;
    const int bm = blockIdx.y * 128;
    const int bn = blockIdx.x * 64;
    const int n  = bm >> 10;
    const int t0 = bm & 1023;

    float c[2][4][4];
    #pragma unroll
    for (int am = 0; am < 2; am++)
        #pragma unroll
        for (int an = 0; an < 4; an++)
            #pragma unroll
            for (int i = 0; i < 4; i++) c[am][an][i] = 0.0f;

    float4 pa[2], pb;
    {
        #pragma unroll
        for (int l = 0; l < 2; l++) {
            int idx = l * 256 + tid;
            int k = idx >> 5, f = idx & 31;
            pa[l] = *(const float4*)&image[n * 262144 + k * 1024 + t0 + f * 4];
        }
        int k = tid >> 4, f = tid & 15;
        pb = *(const float4*)&w[k * 768 + bn + f * 4];
    }

    for (int k0 = 0; k0 < 256; k0 += 16) {
        #pragma unroll
        for (int l = 0; l < 2; l++) {
            int idx = l * 256 + tid;
            int k = idx >> 5, f = idx & 31;
            *(float4*)&As[k * AS_STRIDE + f * 4] = pa[l];
        }
        {
            int k = tid >> 4, f = tid & 15;
            *(float4*)&Bs[k * BS_STRIDE + f * 4] = pb;
        }
        __syncthreads();
        if (k0 + 16 < 256) {
            #pragma unroll
            for (int l = 0; l < 2; l++) {
                int idx = l * 256 + tid;
                int k = idx >> 5, f = idx & 31;
                pa[l] = *(const float4*)&image[n * 262144 + (k0 + 16 + k) * 1024 + t0 + f * 4];
            }
            int k = tid >> 4, f = tid & 15;
            pb = *(const float4*)&w[(k0 + 16 + k) * 768 + bn + f * 4];
        }
        #pragma unroll
        for (int ks = 0; ks < 16; ks += 8) {
            unsigned ahi[2][4], alo[2][4], bhi[4][2], blo[4][2];
            #pragma unroll
            for (int am = 0; am < 2; am++) {
                const int mbase = wm * 32 + am * 16;
                float v0 = As[(ks + tig) * AS_STRIDE + mbase + g];
                float v1 = As[(ks + tig) * AS_STRIDE + mbase + g + 8];
                float v2 = As[(ks + tig + 4) * AS_STRIDE + mbase + g];
                float v3 = As[(ks + tig + 4) * AS_STRIDE + mbase + g + 8];
                tf32_split(v0, ahi[am][0], alo[am][0]);
                tf32_split(v1, ahi[am][1], alo[am][1]);
                tf32_split(v2, ahi[am][2], alo[am][2]);
                tf32_split(v3, ahi[am][3], alo[am][3]);
            }
            #pragma unroll
            for (int an = 0; an < 4; an++) {
                const int nbase = wn * 32 + an * 8;
                float u0 = Bs[(ks + tig) * BS_STRIDE + nbase + g];
                float u1 = Bs[(ks + tig + 4) * BS_STRIDE + nbase + g];
                tf32_split(u0, bhi[an][0], blo[an][0]);
                tf32_split(u1, bhi[an][1], blo[an][1]);
            }
            #pragma unroll
            for (int am = 0; am < 2; am++)
                #pragma unroll
                for (int an = 0; an < 4; an++) {
                    mma_tf32(c[am][an], ahi[am][0], ahi[am][1], ahi[am][2], ahi[am][3],
                             bhi[an][0], bhi[an][1]);
                    mma_tf32(c[am][an], ahi[am][0], ahi[am][1], ahi[am][2], ahi[am][3],
                             blo[an][0], blo[an][1]);
                    mma_tf32(c[am][an], alo[am][0], alo[am][1], alo[am][2], alo[am][3],
                             bhi[an][0], bhi[an][1]);
                }
        }
        __syncthreads();
    }

    #pragma unroll
    for (int an = 0; an < 4; an++) {
        const int o = bn + wn * 32 + an * 8 + 2 * tig;
        const float2 b2 = *(const float2*)&bias[o];
        const int which = o >> 8;
        const int cc = o & 255;
        const int h = cc >> 5;
        const int d0 = cc & 31;
        float* dst = (which == 0) ? g_k : (which == 1) ? g_q : g_v;
        #pragma unroll
        for (int am = 0; am < 2; am++) {
            const int r0 = wm * 32 + am * 16 + g;
            const int t1 = t0 + r0;
            const int t2 = t1 + 8;
            float2 lo = make_float2(c[am][an][0] + b2.x, c[am][an][1] + b2.y);
            float2 hi = make_float2(c[am][an][2] + b2.x, c[am][an][3] + b2.y);
            *(float2*)&dst[((size_t)(n * NHEAD + h) * TSEQ + t1) * HDIM + d0] = lo;
            *(float2*)&dst[((size_t)(n * NHEAD + h) * TSEQ + t2) * HDIM + d0] = hi;
        }
    }
}

// ---------------------------------------------------------------------------
// Kernel 2a: TENSOR-CORE split-K causal flash attention (partials).
// Unit = 64 queries x 128 keys. 72 units/nh, grid (72, 64), 128 threads.
// QK^T via 3xtf32 mma; exp in fragments (no-max, warp-local); PV via 3xtf32
// mma with P staged in smem (A-operand layout) and V pre-split hi/lo.
// Dynamic smem layout (bytes):
//   Qs  [32][68]   fp32   0      .. 8704     (queries pre-scaled, [d][q])
//   Ks  [32][132]  fp32   8704   .. 25600    ([d][key])
//   Vh  [128][40]  fp32   25600  .. 46080    ([key][d] hi)
//   Vl  [128][40]  fp32   46080  .. 66560    ([key][d] lo)
//   Ps  [64][68]   fp32   66560  .. 83968    ([key_loc][q], per chunk)
// ---------------------------------------------------------------------------
#define ATT_SMEM 83968

__global__ __launch_bounds__(128) void attn_tc() {
    extern __shared__ float sm[];
    float* Qs = sm;                 // stride 68
    float* Ks = sm + 2176;          // stride 132
    float* Vh = sm + 6400;          // stride 40
    float* Vl = sm + 11520;         // stride 40
    float* Ps = sm + 16640;         // stride 68

    // unit decode: blockIdx.x in [0,72) -> (qt2, p), p <= qt2/2
    int x = blockIdx.x;
    int qt2 = 0, ubase = 0;
    while (x >= ubase + (qt2 >> 1) + 1) { ubase += (qt2 >> 1) + 1; qt2++; }
    const int p = x - ubase;
    const int nh = blockIdx.y;
    const int tid = threadIdx.x;
    const int lane = tid & 31;
    const int wm = tid >> 5;            // 4 warps, 16 queries each
    const int g = lane >> 2, tig = lane & 3;
    const int bq = qt2 * 64;

    // ---- fills ----
    {   // Q: thread t -> query q = t>>1, d-half = (t&1)*16; scale folded in.
        const int q = tid >> 1, dh = (tid & 1) * 16;
        const float* src = g_q + ((size_t)nh * TSEQ + bq + q) * HDIM + dh;
        #pragma unroll
        for (int i = 0; i < 4; i++) {
            float4 v = *(const float4*)(src + i * 4);
            const float sc = 0.17677669529663687f;
            Qs[(dh + i * 4 + 0) * 68 + q] = v.x * sc;
            Qs[(dh + i * 4 + 1) * 68 + q] = v.y * sc;
            Qs[(dh + i * 4 + 2) * 68 + q] = v.z * sc;
            Qs[(dh + i * 4 + 3) * 68 + q] = v.w * sc;
        }
    }
    {   // K: thread t -> key t (128 keys of slab p)
        const float* src = g_k + ((size_t)nh * TSEQ + p * 128 + tid) * HDIM;
        #pragma unroll
        for (int i = 0; i < 8; i++) {
            float4 v = *(const float4*)(src + i * 4);
            Ks[(i * 4 + 0) * 132 + tid] = v.x;
            Ks[(i * 4 + 1) * 132 + tid] = v.y;
            Ks[(i * 4 + 2) * 132 + tid] = v.z;
            Ks[(i * 4 + 3) * 132 + tid] = v.w;
        }
    }
    {   // V: thread t -> key t, split hi/lo, [key][d] stride 40
        const float* src = g_v + ((size_t)nh * TSEQ + p * 128 + tid) * HDIM;
        #pragma unroll
        for (int i = 0; i < 8; i++) {
            float4 v = *(const float4*)(src + i * 4);
            unsigned hh, ll;
            tf32_split(v.x, hh, ll);
            Vh[tid * 40 + i * 4 + 0] = __uint_as_float(hh); Vl[tid * 40 + i * 4 + 0] = __uint_as_float(ll);
            tf32_split(v.y, hh, ll);
            Vh[tid * 40 + i * 4 + 1] = __uint_as_float(hh); Vl[tid * 40 + i * 4 + 1] = __uint_as_float(ll);
            tf32_split(v.z, hh, ll);
            Vh[tid * 40 + i * 4 + 2] = __uint_as_float(hh); Vl[tid * 40 + i * 4 + 2] = __uint_as_float(ll);
            tf32_split(v.w, hh, ll);
            Vh[tid * 40 + i * 4 + 3] = __uint_as_float(hh); Vl[tid * 40 + i * 4 + 3] = __uint_as_float(ll);
        }
    }
    __syncthreads();

    float o_acc[4][4];
    #pragma unroll
    for (int an = 0; an < 4; an++)
        #pragma unroll
        for (int i = 0; i < 4; i++) o_acc[an][i] = 0.0f;
    float ls0 = 0.0f, ls1 = 0.0f;

    const int mq = wm * 16;             // this warp's query base (local)
    const int q0 = bq + mq + g;         // global query rows q0, q0+8

    for (int chunk = 0; chunk < 2; chunk++) {
        if (p * 128 + chunk * 64 > qt2 * 64 + 63) break;   // fully masked (uniform)
        const int ck = chunk * 64;

        // ---- QK^T: S[16q x 64k] in fragments s[8][4] ----
        float s[8][4];
        #pragma unroll
        for (int an = 0; an < 8; an++)
            #pragma unroll
            for (int i = 0; i < 4; i++) s[an][i] = 0.0f;

        #pragma unroll
        for (int ks = 0; ks < 4; ks++) {
            const int kr0 = ks * 8 + tig, kr1 = kr0 + 4;
            unsigned ah[4], al[4];
            tf32_split(Qs[kr0 * 68 + mq + g],     ah[0], al[0]);
            tf32_split(Qs[kr0 * 68 + mq + g + 8], ah[1], al[1]);
            tf32_split(Qs[kr1 * 68 + mq + g],     ah[2], al[2]);
            tf32_split(Qs[kr1 * 68 + mq + g + 8], ah[3], al[3]);
            #pragma unroll
            for (int an = 0; an < 8; an++) {
                unsigned bh0, bl0, bh1, bl1;
                tf32_split(Ks[kr0 * 132 + ck + an * 8 + g], bh0, bl0);
                tf32_split(Ks[kr1 * 132 + ck + an * 8 + g], bh1, bl1);
                mma_tf32(s[an], ah[0], ah[1], ah[2], ah[3], bh0, bh1);
                mma_tf32(s[an], ah[0], ah[1], ah[2], ah[3], bl0, bl1);
                mma_tf32(s[an], al[0], al[1], al[2], al[3], bh0, bh1);
            }
        }

        // ---- epilogue: causal mask + exp (no-max) + lsum + store P ----
        #pragma unroll
        for (int an = 0; an < 8; an++) {
            const int key0 = p * 128 + ck + an * 8 + 2 * tig;
            float e0 = __expf(s[an][0]);
            float e1 = __expf(s[an][1]);
            float e2 = __expf(s[an][2]);
            float e3 = __expf(s[an][3]);
            if (key0     > q0)     e0 = 0.0f;
            if (key0 + 1 > q0)     e1 = 0.0f;
            if (key0     > q0 + 8) e2 = 0.0f;
            if (key0 + 1 > q0 + 8) e3 = 0.0f;
            ls0 += e0 + e1;
            ls1 += e2 + e3;
            const int kl = an * 8 + 2 * tig;
            Ps[(kl    ) * 68 + mq + g    ] = e0;
            Ps[(kl + 1) * 68 + mq + g    ] = e1;
            Ps[(kl    ) * 68 + mq + g + 8] = e2;
            Ps[(kl + 1) * 68 + mq + g + 8] = e3;
        }
        __syncwarp();

        // ---- PV: O += P[16q x 64k] * V[64k x 32d], 3xtf32 ----
        #pragma unroll
        for (int ks = 0; ks < 8; ks++) {
            const int kr0 = ks * 8 + tig, kr1 = kr0 + 4;
            unsigned ph[4], pl[4];
            tf32_split(Ps[kr0 * 68 + mq + g],     ph[0], pl[0]);
            tf32_split(Ps[kr0 * 68 + mq + g + 8], ph[1], pl[1]);
            tf32_split(Ps[kr1 * 68 + mq + g],     ph[2], pl[2]);
            tf32_split(Ps[kr1 * 68 + mq + g + 8], ph[3], pl[3]);
            const int vr0 = ck + kr0, vr1 = ck + kr1;
            #pragma unroll
            for (int an = 0; an < 4; an++) {
                unsigned bh0 = __float_as_uint(Vh[vr0 * 40 + an * 8 + g]);
                unsigned bh1 = __float_as_uint(Vh[vr1 * 40 + an * 8 + g]);
                unsigned bl0 = __float_as_uint(Vl[vr0 * 40 + an * 8 + g]);
                unsigned bl1 = __float_as_uint(Vl[vr1 * 40 + an * 8 + g]);
                mma_tf32(o_acc[an], ph[0], ph[1], ph[2], ph[3], bh0, bh1);
                mma_tf32(o_acc[an], ph[0], ph[1], ph[2], ph[3], bl0, bl1);
                mma_tf32(o_acc[an], pl[0], pl[1], pl[2], pl[3], bh0, bh1);
            }
        }
        __syncwarp();   // before Ps is overwritten next chunk (warp-local)
    }

    // ---- write partials: pacc[nh][unit][d(32)][q(64)], plsum ----
    float* pout = g_pacc + ((size_t)(nh * 72 + blockIdx.x) * 32) * 64;
    #pragma unroll
    for (int an = 0; an < 4; an++) {
        const int d0 = an * 8 + 2 * tig;
        const int ql = mq + g;
        pout[(d0    ) * 64 + ql    ] = o_acc[an][0];
        pout[(d0 + 1) * 64 + ql    ] = o_acc[an][1];
        pout[(d0    ) * 64 + ql + 8] = o_acc[an][2];
        pout[(d0 + 1) * 64 + ql + 8] = o_acc[an][3];
    }
    // lsum: sum over tig lanes (lane bits 0,1)
    ls0 += __shfl_xor_sync(0xFFFFFFFF, ls0, 1);
    ls0 += __shfl_xor_sync(0xFFFFFFFF, ls0, 2);
    ls1 += __shfl_xor_sync(0xFFFFFFFF, ls1, 1);
    ls1 += __shfl_xor_sync(0xFFFFFFFF, ls1, 2);
    if (tig == 0) {
        float* lout = g_plsum + (size_t)(nh * 72 + blockIdx.x) * 64;
        lout[mq + g]     = ls0;
        lout[mq + g + 8] = ls1;
    }
}

// ---------------------------------------------------------------------------
// Kernel 2b: per-query inverse lsum. (nh, qt2, q): 64*16*64 = 65536 threads.
// ---------------------------------------------------------------------------
__global__ __launch_bounds__(256) void attn_inv() {
    const int t = blockIdx.x * 256 + threadIdx.x;
    const int q   = t & 63;
    const int qt2 = (t >> 6) & 15;
    const int nh  = t >> 10;
    const int m = qt2 >> 1;
    const int base = (qt2 & 1) ? (m + 1) * (m + 1) : m * (m + 1);
    const int npart = m + 1;

    float lsum = 0.0f;
    for (int pp = 0; pp < npart; pp++)
        lsum += g_plsum[(size_t)(nh * 72 + base + pp) * 64 + q];
    g_inv[t] = 1.0f / lsum;
}

// ---------------------------------------------------------------------------
// Kernel 2c: element-parallel reduce -> g_attn [C, N*T]. 2.1M threads.
// ---------------------------------------------------------------------------
__global__ __launch_bounds__(256) void attn_reduce2() {
    const int t = blockIdx.x * 256 + threadIdx.x;    // 2097152
    const int q   = t & 63;
    const int d   = (t >> 6) & 31;
    const int qt2 = (t >> 11) & 15;
    const int nh  = t >> 15;
    const int m = qt2 >> 1;
    const int base = (qt2 & 1) ? (m + 1) * (m + 1) : m * (m + 1);
    const int npart = m + 1;

    float acc = 0.0f;
    const float* pin = g_pacc + ((size_t)(nh * 72 + base) * 32 + d) * 64 + q;
    #pragma unroll 4
    for (int pp = 0; pp < npart; pp++)
        acc += pin[(size_t)pp * 32 * 64];

    const float inv = g_inv[(nh * 16 + qt2) * 64 + q];
    const int n = nh >> 3;
    const int h = nh & 7;
    const int tq = qt2 * 64 + q;
    g_attn[(size_t)(h * HDIM + d) * (NBATCH * TSEQ) + (size_t)n * TSEQ + tq] = acc * inv;
}

// ---------------------------------------------------------------------------
// Kernel 3: mix + bias + residual via 3xTF32 mma.sync (R7-R11 proven).
// ---------------------------------------------------------------------------
__global__ __launch_bounds__(256) void mix_mma(const float* __restrict__ image,
                                               const float* __restrict__ w,
                                               const float* __restrict__ bias,
                                               float* __restrict__ out) {
    __shared__ float As[16 * AS_STRIDE];
    __shared__ float Bs[16 * BS_STRIDE];
    const int tid = threadIdx.x;
    const int lane = tid & 31;
    const int wid = tid >> 5;
    const int wm = wid & 3;
    const int wn = wid >> 2;
    const int g = lane >> 2, tig = lane & 3;
    const int bm = blockIdx.y * 128;
    const int bn = blockIdx.x * 64;
    const int n  = bm >> 10;
    const int t0 = bm & 1023;

    float c[2][4][4];
    #pragma unroll
    for (int am = 0; am < 2; am++)
        #pragma unroll
        for (int an = 0; an < 4; an++)
            #pragma unroll
            for (int i = 0; i < 4; i++) c[am][an][i] = 0.0f;

    float4 pa[2], pb;
    {
        #pragma unroll
        for (int l = 0; l < 2; l++) {
            int idx = l * 256 + tid;
            int k = idx >> 5, f = idx & 31;
            pa[l] = *(const float4*)&g_attn[(size_t)k * 8192 + bm + f * 4];
        }
        int k = tid >> 4, f = tid & 15;
        pb = *(const float4*)&w[k * 256 + bn + f * 4];
    }

    for (int k0 = 0; k0 < 256; k0 += 16) {
        #pragma unroll
        for (int l = 0; l < 2; l++) {
            int idx = l * 256 + tid;
            int k = idx >> 5, f = idx & 31;
            *(float4*)&As[k * AS_STRIDE + f * 4] = pa[l];
        }
        {
            int k = tid >> 4, f = tid & 15;
            *(float4*)&Bs[k * BS_STRIDE + f * 4] = pb;
        }
        __syncthreads();
        if (k0 + 16 < 256) {
            #pragma unroll
            for (int l = 0; l < 2; l++) {
                int idx = l * 256 + tid;
                int k = idx >> 5, f = idx & 31;
                pa[l] = *(const float4*)&g_attn[(size_t)(k0 + 16 + k) * 8192 + bm + f * 4];
            }
            int k = tid >> 4, f = tid & 15;
            pb = *(const float4*)&w[(k0 + 16 + k) * 256 + bn + f * 4];
        }
        #pragma unroll
        for (int ks = 0; ks < 16; ks += 8) {
            unsigned ahi[2][4], alo[2][4], bhi[4][2], blo[4][2];
            #pragma unroll
            for (int am = 0; am < 2; am++) {
                const int mbase = wm * 32 + am * 16;
                float v0 = As[(ks + tig) * AS_STRIDE + mbase + g];
                float v1 = As[(ks + tig) * AS_STRIDE + mbase + g + 8];
                float v2 = As[(ks + tig + 4) * AS_STRIDE + mbase + g];
                float v3 = As[(ks + tig + 4) * AS_STRIDE + mbase + g + 8];
                tf32_split(v0, ahi[am][0], alo[am][0]);
                tf32_split(v1, ahi[am][1], alo[am][1]);
                tf32_split(v2, ahi[am][2], alo[am][2]);
                tf32_split(v3, ahi[am][3], alo[am][3]);
            }
            #pragma unroll
            for (int an = 0; an < 4; an++) {
                const int nbase = wn * 32 + an * 8;
                float u0 = Bs[(ks + tig) * BS_STRIDE + nbase + g];
                float u1 = Bs[(ks + tig + 4) * BS_STRIDE + nbase + g];
                tf32_split(u0, bhi[an][0], blo[an][0]);
                tf32_split(u1, bhi[an][1], blo[an][1]);
            }
            #pragma unroll
            for (int am = 0; am < 2; am++)
                #pragma unroll
                for (int an = 0; an < 4; an++) {
                    mma_tf32(c[am][an], ahi[am][0], ahi[am][1], ahi[am][2], ahi[am][3],
                             bhi[an][0], bhi[an][1]);
                    mma_tf32(c[am][an], ahi[am][0], ahi[am][1], ahi[am][2], ahi[am][3],
                             blo[an][0], blo[an][1]);
                    mma_tf32(c[am][an], alo[am][0], alo[am][1], alo[am][2], alo[am][3],
                             bhi[an][0], bhi[an][1]);
                }
        }
        __syncthreads();
    }

    #pragma unroll
    for (int an = 0; an < 4; an++) {
        const int o = bn + wn * 32 + an * 8 + 2 * tig;
        const float2 b2 = *(const float2*)&bias[o];
        #pragma unroll
        for (int am = 0; am < 2; am++) {
            const int r0 = wm * 32 + am * 16 + g;
            const int t1 = t0 + r0;
            const size_t g00 = (size_t)n * 262144 + (size_t)o * 1024 + t1;
            const size_t g01 = g00 + 1024;
            out[g00]     = c[am][an][0] + b2.x + image[g00];
            out[g01]     = c[am][an][1] + b2.y + image[g01];
            out[g00 + 8] = c[am][an][2] + b2.x + image[g00 + 8];
            out[g01 + 8] = c[am][an][3] + b2.y + image[g01 + 8];
        }
    }
}

// ---------------------------------------------------------------------------
extern "C" void kernel_launch(void* const* d_in, const int* in_sizes, int n_in,
                              void* d_out, int out_size) {
    const float* image = (const float*)d_in[0];
    const float* w_kqv = (const float*)d_in[1];
    const float* b_kqv = (const float*)d_in[2];
    const float* w_mix = (const float*)d_in[3];
    const float* b_mix = (const float*)d_in[4];
    float* out = (float*)d_out;

    cudaFuncSetAttribute(attn_tc, cudaFuncAttributeMaxDynamicSharedMemorySize,
                         ATT_SMEM);

    dim3 gridA(768 / 64, 8192 / 128);
    kqv_mma<<<gridA, 256>>>(image, w_kqv, b_kqv);

    dim3 gridB(72, 64);
    attn_tc<<<gridB, 128, ATT_SMEM>>>();

    attn_inv<<<256, 256>>>();
    attn_reduce2<<<8192, 256>>>();

    dim3 gridC(256 / 64, 8192 / 128);
    mix_mma<<<gridC, 256>>>(image, w_mix, b_mix, out);
}

// round 13
// speedup vs baseline: 1.2862x; 1.1570x over previous
#include <cuda_runtime.h>
#include <math.h>

// Problem constants
#define NBATCH 8
#define CCH    256
#define TSEQ   1024
#define NHEAD  8
#define HDIM   32

// ---- tf32 mma primitives ----
__device__ __forceinline__ unsigned tf32_of(float x) {
    unsigned r; asm("cvt.rna.tf32.f32 %0, %1;" : "=r"(r) : "f"(x)); return r;
}
__device__ __forceinline__ void tf32_split(float v, unsigned& hi, unsigned& lo) {
    hi = tf32_of(v);
    lo = tf32_of(v - __uint_as_float(hi));
}
__device__ __forceinline__ void mma_tf32(float c[4],
                                         unsigned a0, unsigned a1, unsigned a2, unsigned a3,
                                         unsigned b0, unsigned b1) {
    asm("mma.sync.aligned.m16n8k8.row.col.f32.tf32.tf32.f32 "
        "{%0,%1,%2,%3}, {%4,%5,%6,%7}, {%8,%9}, {%0,%1,%2,%3};"
        : "+f"(c[0]), "+f"(c[1]), "+f"(c[2]), "+f"(c[3])
        : "r"(a0), "r"(a1), "r"(a2), "r"(a3), "r"(b0), "r"(b1));
}

// Scratch. K/Q/V in [N, H, T, D]. g_attn TRANSPOSED: [C, N*T].
__device__ float g_k[NBATCH * NHEAD * TSEQ * HDIM];
__device__ float g_q[NBATCH * NHEAD * TSEQ * HDIM];
__device__ float g_v[NBATCH * NHEAD * TSEQ * HDIM];
__device__ float g_attn[CCH * NBATCH * TSEQ];
// Split-K partials: 36 units/nh of 128 queries x 128 keys.
__device__ float g_pacc[64 * 36 * 32 * 128];
__device__ float g_plsum[64 * 36 * 128];
__device__ float g_inv[64 * 8 * 128];     // 1/lsum per (nh, qt, q)

#define AS_STRIDE 136
#define BS_STRIDE 72

// ---------------------------------------------------------------------------
// Kernel 1: KQV projection via 3xTF32 mma.sync (R7-R12 proven).
// ---------------------------------------------------------------------------
__global__ __launch_bounds__(256) void kqv_mma(const float* __restrict__ image,
                                               const float* __restrict__ w,
                                               const float* __restrict__ bias) {
    __shared__ float As[16 * AS_STRIDE];
    __shared__ float Bs[16 * BS_STRIDE];
    const int tid = threadIdx.x;
    const int lane = tid & 31;
    const int wid = tid >> 5;
    const int wm = wid & 3;
    const int wn = wid >> 2;
    const int g = lane >> 2, tig = lane & 3;
    const int bm = blockIdx.y * 128;
    const int bn = blockIdx.x * 64;
    const int n  = bm >> 10;
    const int t0 = bm & 1023;

    float c[2][4][4];
    #pragma unroll
    for (int am = 0; am < 2; am++)
        #pragma unroll
        for (int an = 0; an < 4; an++)
            #pragma unroll
            for (int i = 0; i < 4; i++) c[am][an][i] = 0.0f;

    float4 pa[2], pb;
    {
        #pragma unroll
        for (int l = 0; l < 2; l++) {
            int idx = l * 256 + tid;
            int k = idx >> 5, f = idx & 31;
            pa[l] = *(const float4*)&image[n * 262144 + k * 1024 + t0 + f * 4];
        }
        int k = tid >> 4, f = tid & 15;
        pb = *(const float4*)&w[k * 768 + bn + f * 4];
    }

    for (int k0 = 0; k0 < 256; k0 += 16) {
        #pragma unroll
        for (int l = 0; l < 2; l++) {
            int idx = l * 256 + tid;
            int k = idx >> 5, f = idx & 31;
            *(float4*)&As[k * AS_STRIDE + f * 4] = pa[l];
        }
        {
            int k = tid >> 4, f = tid & 15;
            *(float4*)&Bs[k * BS_STRIDE + f * 4] = pb;
        }
        __syncthreads();
        if (k0 + 16 < 256) {
            #pragma unroll
            for (int l = 0; l < 2; l++) {
                int idx = l * 256 + tid;
                int k = idx >> 5, f = idx & 31;
                pa[l] = *(const float4*)&image[n * 262144 + (k0 + 16 + k) * 1024 + t0 + f * 4];
            }
            int k = tid >> 4, f = tid & 15;
            pb = *(const float4*)&w[(k0 + 16 + k) * 768 + bn + f * 4];
        }
        #pragma unroll
        for (int ks = 0; ks < 16; ks += 8) {
            unsigned ahi[2][4], alo[2][4], bhi[4][2], blo[4][2];
            #pragma unroll
            for (int am = 0; am < 2; am++) {
                const int mbase = wm * 32 + am * 16;
                float v0 = As[(ks + tig) * AS_STRIDE + mbase + g];
                float v1 = As[(ks + tig) * AS_STRIDE + mbase + g + 8];
                float v2 = As[(ks + tig + 4) * AS_STRIDE + mbase + g];
                float v3 = As[(ks + tig + 4) * AS_STRIDE + mbase + g + 8];
                tf32_split(v0, ahi[am][0], alo[am][0]);
                tf32_split(v1, ahi[am][1], alo[am][1]);
                tf32_split(v2, ahi[am][2], alo[am][2]);
                tf32_split(v3, ahi[am][3], alo[am][3]);
            }
            #pragma unroll
            for (int an = 0; an < 4; an++) {
                const int nbase = wn * 32 + an * 8;
                float u0 = Bs[(ks + tig) * BS_STRIDE + nbase + g];
                float u1 = Bs[(ks + tig + 4) * BS_STRIDE + nbase + g];
                tf32_split(u0, bhi[an][0], blo[an][0]);
                tf32_split(u1, bhi[an][1], blo[an][1]);
            }
            #pragma unroll
            for (int am = 0; am < 2; am++)
                #pragma unroll
                for (int an = 0; an < 4; an++) {
                    mma_tf32(c[am][an], ahi[am][0], ahi[am][1], ahi[am][2], ahi[am][3],
                             bhi[an][0], bhi[an][1]);
                    mma_tf32(c[am][an], ahi[am][0], ahi[am][1], ahi[am][2], ahi[am][3],
                             blo[an][0], blo[an][1]);
                    mma_tf32(c[am][an], alo[am][0], alo[am][1], alo[am][2], alo[am][3],
                             bhi[an][0], bhi[an][1]);
                }
        }
        __syncthreads();
    }

    #pragma unroll
    for (int an = 0; an < 4; an++) {
        const int o = bn + wn * 32 + an * 8 + 2 * tig;
        const float2 b2 = *(const float2*)&bias[o];
        const int which = o >> 8;
        const int cc = o & 255;
        const int h = cc >> 5;
        const int d0 = cc & 31;
        float* dst = (which == 0) ? g_k : (which == 1) ? g_q : g_v;
        #pragma unroll
        for (int am = 0; am < 2; am++) {
            const int r0 = wm * 32 + am * 16 + g;
            const int t1 = t0 + r0;
            const int t2 = t1 + 8;
            float2 lo = make_float2(c[am][an][0] + b2.x, c[am][an][1] + b2.y);
            float2 hi = make_float2(c[am][an][2] + b2.x, c[am][an][3] + b2.y);
            *(float2*)&dst[((size_t)(n * NHEAD + h) * TSEQ + t1) * HDIM + d0] = lo;
            *(float2*)&dst[((size_t)(n * NHEAD + h) * TSEQ + t2) * HDIM + d0] = hi;
        }
    }
}

// ---------------------------------------------------------------------------
// Kernel 2a: TENSOR-CORE split-K causal flash attention.
// Unit = 128 queries x 128 keys; 36 units/nh; grid (36, 64); 256 threads
// (8 warps x 16 queries). All fragment strides = 136 (conflict-free).
// Dynamic smem (floats):
//   Qs [32][136]  @0       (queries pre-scaled, [d][q])
//   Ks [32][136]  @4352    ([d][key])
//   Vh [128][40]  @8704    ([key][d] hi)
//   Vl [128][40]  @13824   ([key][d] lo)
//   Ps [64][136]  @18944   ([key_loc][q], per 64-key chunk)
// Total 27648 floats = 110592 bytes.
// ---------------------------------------------------------------------------
#define ATT_SMEM 110592

__global__ __launch_bounds__(256) void attn_tc() {
    extern __shared__ float sm[];
    float* Qs = sm;                 // stride 136
    float* Ks = sm + 4352;          // stride 136
    float* Vh = sm + 8704;          // stride 40
    float* Vl = sm + 13824;         // stride 40
    float* Ps = sm + 18944;         // stride 136

    // unit decode: x = qt(qt+1)/2 + p, p <= qt
    int x = blockIdx.x;
    int qt = 0, ubase = 0;
    while (x >= ubase + qt + 1) { ubase += qt + 1; qt++; }
    const int p = x - ubase;
    const int nh = blockIdx.y;
    const int tid = threadIdx.x;
    const int lane = tid & 31;
    const int wm = tid >> 5;            // 8 warps, 16 queries each
    const int g = lane >> 2, tig = lane & 3;
    const int bq = qt * 128;

    // ---- fills (256 threads) ----
    {   // Q: t -> query q = t>>1, d-half = (t&1)*16; scale folded in.
        const int q = tid >> 1, dh = (tid & 1) * 16;
        const float* src = g_q + ((size_t)nh * TSEQ + bq + q) * HDIM + dh;
        const float sc = 0.17677669529663687f;
        #pragma unroll
        for (int i = 0; i < 4; i++) {
            float4 v = *(const float4*)(src + i * 4);
            Qs[(dh + i * 4 + 0) * 136 + q] = v.x * sc;
            Qs[(dh + i * 4 + 1) * 136 + q] = v.y * sc;
            Qs[(dh + i * 4 + 2) * 136 + q] = v.z * sc;
            Qs[(dh + i * 4 + 3) * 136 + q] = v.w * sc;
        }
    }
    {   // K: t -> key = t>>1, d-half = (t&1)*16
        const int k = tid >> 1, dh = (tid & 1) * 16;
        const float* src = g_k + ((size_t)nh * TSEQ + p * 128 + k) * HDIM + dh;
        #pragma unroll
        for (int i = 0; i < 4; i++) {
            float4 v = *(const float4*)(src + i * 4);
            Ks[(dh + i * 4 + 0) * 136 + k] = v.x;
            Ks[(dh + i * 4 + 1) * 136 + k] = v.y;
            Ks[(dh + i * 4 + 2) * 136 + k] = v.z;
            Ks[(dh + i * 4 + 3) * 136 + k] = v.w;
        }
    }
    {   // V: t -> key = t>>1, d-half = (t&1)*16; split hi/lo, [key][d] stride 40
        const int k = tid >> 1, dh = (tid & 1) * 16;
        const float* src = g_v + ((size_t)nh * TSEQ + p * 128 + k) * HDIM + dh;
        #pragma unroll
        for (int i = 0; i < 4; i++) {
            float4 v = *(const float4*)(src + i * 4);
            unsigned hh, ll;
            tf32_split(v.x, hh, ll);
            Vh[k * 40 + dh + i * 4 + 0] = __uint_as_float(hh); Vl[k * 40 + dh + i * 4 + 0] = __uint_as_float(ll);
            tf32_split(v.y, hh, ll);
            Vh[k * 40 + dh + i * 4 + 1] = __uint_as_float(hh); Vl[k * 40 + dh + i * 4 + 1] = __uint_as_float(ll);
            tf32_split(v.z, hh, ll);
            Vh[k * 40 + dh + i * 4 + 2] = __uint_as_float(hh); Vl[k * 40 + dh + i * 4 + 2] = __uint_as_float(ll);
            tf32_split(v.w, hh, ll);
            Vh[k * 40 + dh + i * 4 + 3] = __uint_as_float(hh); Vl[k * 40 + dh + i * 4 + 3] = __uint_as_float(ll);
        }
    }
    __syncthreads();

    float o_acc[4][4];
    #pragma unroll
    for (int an = 0; an < 4; an++)
        #pragma unroll
        for (int i = 0; i < 4; i++) o_acc[an][i] = 0.0f;
    float ls0 = 0.0f, ls1 = 0.0f;

    const int mq = wm * 16;             // this warp's query base (local)
    const int q0 = bq + mq + g;         // global query rows q0, q0+8
    const bool diag = (p == qt);

    #pragma unroll
    for (int chunk = 0; chunk < 2; chunk++) {
        const int ck = chunk * 64;

        // ---- QK^T: S[16q x 64k] fragments s[8][4] ----
        float s[8][4];
        #pragma unroll
        for (int an = 0; an < 8; an++)
            #pragma unroll
            for (int i = 0; i < 4; i++) s[an][i] = 0.0f;

        #pragma unroll
        for (int ks = 0; ks < 4; ks++) {
            const int kr0 = ks * 8 + tig, kr1 = kr0 + 4;
            unsigned ah[4], al[4];
            tf32_split(Qs[kr0 * 136 + mq + g],     ah[0], al[0]);
            tf32_split(Qs[kr0 * 136 + mq + g + 8], ah[1], al[1]);
            tf32_split(Qs[kr1 * 136 + mq + g],     ah[2], al[2]);
            tf32_split(Qs[kr1 * 136 + mq + g + 8], ah[3], al[3]);
            #pragma unroll
            for (int an = 0; an < 8; an++) {
                unsigned bh0, bl0, bh1, bl1;
                tf32_split(Ks[kr0 * 136 + ck + an * 8 + g], bh0, bl0);
                tf32_split(Ks[kr1 * 136 + ck + an * 8 + g], bh1, bl1);
                mma_tf32(s[an], ah[0], ah[1], ah[2], ah[3], bh0, bh1);
                mma_tf32(s[an], ah[0], ah[1], ah[2], ah[3], bl0, bl1);
                mma_tf32(s[an], al[0], al[1], al[2], al[3], bh0, bh1);
            }
        }

        // ---- epilogue: exp (no-max) + causal SEL (diag only) + lsum + P ----
        #pragma unroll
        for (int an = 0; an < 8; an++) {
            float e0 = __expf(s[an][0]);
            float e1 = __expf(s[an][1]);
            float e2 = __expf(s[an][2]);
            float e3 = __expf(s[an][3]);
            if (diag) {
                const int key0 = p * 128 + ck + an * 8 + 2 * tig;
                if (key0     > q0)     e0 = 0.0f;
                if (key0 + 1 > q0)     e1 = 0.0f;
                if (key0     > q0 + 8) e2 = 0.0f;
                if (key0 + 1 > q0 + 8) e3 = 0.0f;
            }
            ls0 += e0 + e1;
            ls1 += e2 + e3;
            const int kl = an * 8 + 2 * tig;
            Ps[(kl    ) * 136 + mq + g    ] = e0;
            Ps[(kl + 1) * 136 + mq + g    ] = e1;
            Ps[(kl    ) * 136 + mq + g + 8] = e2;
            Ps[(kl + 1) * 136 + mq + g + 8] = e3;
        }
        __syncwarp();

        // ---- PV: O += P[16q x 64k] * V[64k x 32d] ----
        #pragma unroll
        for (int ks = 0; ks < 8; ks++) {
            const int kr0 = ks * 8 + tig, kr1 = kr0 + 4;
            unsigned ph[4], pl[4];
            tf32_split(Ps[kr0 * 136 + mq + g],     ph[0], pl[0]);
            tf32_split(Ps[kr0 * 136 + mq + g + 8], ph[1], pl[1]);
            tf32_split(Ps[kr1 * 136 + mq + g],     ph[2], pl[2]);
            tf32_split(Ps[kr1 * 136 + mq + g + 8], ph[3], pl[3]);
            const int vr0 = ck + kr0, vr1 = ck + kr1;
            #pragma unroll
            for (int an = 0; an < 4; an++) {
                unsigned bh0 = __float_as_uint(Vh[vr0 * 40 + an * 8 + g]);
                unsigned bh1 = __float_as_uint(Vh[vr1 * 40 + an * 8 + g]);
                unsigned bl0 = __float_as_uint(Vl[vr0 * 40 + an * 8 + g]);
                unsigned bl1 = __float_as_uint(Vl[vr1 * 40 + an * 8 + g]);
                mma_tf32(o_acc[an], ph[0], ph[1], ph[2], ph[3], bh0, bh1);
                mma_tf32(o_acc[an], ph[0], ph[1], ph[2], ph[3], bl0, bl1);
                mma_tf32(o_acc[an], pl[0], pl[1], pl[2], pl[3], bh0, bh1);
            }
        }
        __syncwarp();   // Ps reused next chunk (warp-local columns)
    }

    // ---- write partials: pacc[nh][unit][d(32)][q(128)] ----
    float* pout = g_pacc + ((size_t)(nh * 36 + blockIdx.x) * 32) * 128;
    #pragma unroll
    for (int an = 0; an < 4; an++) {
        const int d0 = an * 8 + 2 * tig;
        const int ql = mq + g;
        pout[(d0    ) * 128 + ql    ] = o_acc[an][0];
        pout[(d0 + 1) * 128 + ql    ] = o_acc[an][1];
        pout[(d0    ) * 128 + ql + 8] = o_acc[an][2];
        pout[(d0 + 1) * 128 + ql + 8] = o_acc[an][3];
    }
    // lsum: reduce over tig (lane bits 0,1)
    ls0 += __shfl_xor_sync(0xFFFFFFFF, ls0, 1);
    ls0 += __shfl_xor_sync(0xFFFFFFFF, ls0, 2);
    ls1 += __shfl_xor_sync(0xFFFFFFFF, ls1, 1);
    ls1 += __shfl_xor_sync(0xFFFFFFFF, ls1, 2);
    if (tig == 0) {
        float* lout = g_plsum + (size_t)(nh * 36 + blockIdx.x) * 128;
        lout[mq + g]     = ls0;
        lout[mq + g + 8] = ls1;
    }
}

// ---------------------------------------------------------------------------
// Kernel 2b: per-query inverse lsum (R11-proven). 65536 threads: (nh, qt, q).
// ---------------------------------------------------------------------------
__global__ __launch_bounds__(256) void attn_inv() {
    const int t = blockIdx.x * 256 + threadIdx.x;
    const int q  = t & 127;
    const int qt = (t >> 7) & 7;
    const int nh = t >> 10;
    const int base = qt * (qt + 1) / 2;

    float lsum = 0.0f;
    for (int p = 0; p <= qt; p++)
        lsum += g_plsum[(size_t)(nh * 36 + base + p) * 128 + q];
    g_inv[t] = 1.0f / lsum;
}

// ---------------------------------------------------------------------------
// Kernel 2c: element-parallel reduce -> g_attn [C, N*T] (R11-proven).
// ---------------------------------------------------------------------------
__global__ __launch_bounds__(256) void attn_reduce2() {
    const int t = blockIdx.x * 256 + threadIdx.x;   // 2097152 total
    const int q  = t & 127;
    const int d  = (t >> 7) & 31;
    const int qt = (t >> 12) & 7;
    const int nh = t >> 15;
    const int base = qt * (qt + 1) / 2;

    float acc = 0.0f;
    const float* pin = g_pacc + ((size_t)(nh * 36 + base) * 32 + d) * 128 + q;
    #pragma unroll 4
    for (int p = 0; p <= qt; p++)
        acc += pin[(size_t)p * 32 * 128];

    const float inv = g_inv[(nh * 8 + qt) * 128 + q];
    const int n = nh >> 3;
    const int h = nh & 7;
    const int tq = qt * 128 + q;
    g_attn[(size_t)(h * HDIM + d) * (NBATCH * TSEQ) + (size_t)n * TSEQ + tq] = acc * inv;
}

// ---------------------------------------------------------------------------
// Kernel 3: mix + bias + residual via 3xTF32 mma.sync (R7-R12 proven).
// ---------------------------------------------------------------------------
__global__ __launch_bounds__(256) void mix_mma(const float* __restrict__ image,
                                               const float* __restrict__ w,
                                               const float* __restrict__ bias,
                                               float* __restrict__ out) {
    __shared__ float As[16 * AS_STRIDE];
    __shared__ float Bs[16 * BS_STRIDE];
    const int tid = threadIdx.x;
    const int lane = tid & 31;
    const int wid = tid >> 5;
    const int wm = wid & 3;
    const int wn = wid >> 2;
    const int g = lane >> 2, tig = lane & 3;
    const int bm = blockIdx.y * 128;
    const int bn = blockIdx.x * 64;
    const int n  = bm >> 10;
    const int t0 = bm & 1023;

    float c[2][4][4];
    #pragma unroll
    for (int am = 0; am < 2; am++)
        #pragma unroll
        for (int an = 0; an < 4; an++)
            #pragma unroll
            for (int i = 0; i < 4; i++) c[am][an][i] = 0.0f;

    float4 pa[2], pb;
    {
        #pragma unroll
        for (int l = 0; l < 2; l++) {
            int idx = l * 256 + tid;
            int k = idx >> 5, f = idx & 31;
            pa[l] = *(const float4*)&g_attn[(size_t)k * 8192 + bm + f * 4];
        }
        int k = tid >> 4, f = tid & 15;
        pb = *(const float4*)&w[k * 256 + bn + f * 4];
    }

    for (int k0 = 0; k0 < 256; k0 += 16) {
        #pragma unroll
        for (int l = 0; l < 2; l++) {
            int idx = l * 256 + tid;
            int k = idx >> 5, f = idx & 31;
            *(float4*)&As[k * AS_STRIDE + f * 4] = pa[l];
        }
        {
            int k = tid >> 4, f = tid & 15;
            *(float4*)&Bs[k * BS_STRIDE + f * 4] = pb;
        }
        __syncthreads();
        if (k0 + 16 < 256) {
            #pragma unroll
            for (int l = 0; l < 2; l++) {
                int idx = l * 256 + tid;
                int k = idx >> 5, f = idx & 31;
                pa[l] = *(const float4*)&g_attn[(size_t)(k0 + 16 + k) * 8192 + bm + f * 4];
            }
            int k = tid >> 4, f = tid & 15;
            pb = *(const float4*)&w[(k0 + 16 + k) * 256 + bn + f * 4];
        }
        #pragma unroll
        for (int ks = 0; ks < 16; ks += 8) {
            unsigned ahi[2][4], alo[2][4], bhi[4][2], blo[4][2];
            #pragma unroll
            for (int am = 0; am < 2; am++) {
                const int mbase = wm * 32 + am * 16;
                float v0 = As[(ks + tig) * AS_STRIDE + mbase + g];
                float v1 = As[(ks + tig) * AS_STRIDE + mbase + g + 8];
                float v2 = As[(ks + tig + 4) * AS_STRIDE + mbase + g];
                float v3 = As[(ks + tig + 4) * AS_STRIDE + mbase + g + 8];
                tf32_split(v0, ahi[am][0], alo[am][0]);
                tf32_split(v1, ahi[am][1], alo[am][1]);
                tf32_split(v2, ahi[am][2], alo[am][2]);
                tf32_split(v3, ahi[am][3], alo[am][3]);
            }
            #pragma unroll
            for (int an = 0; an < 4; an++) {
                const int nbase = wn * 32 + an * 8;
                float u0 = Bs[(ks + tig) * BS_STRIDE + nbase + g];
                float u1 = Bs[(ks + tig + 4) * BS_STRIDE + nbase + g];
                tf32_split(u0, bhi[an][0], blo[an][0]);
                tf32_split(u1, bhi[an][1], blo[an][1]);
            }
            #pragma unroll
            for (int am = 0; am < 2; am++)
                #pragma unroll
                for (int an = 0; an < 4; an++) {
                    mma_tf32(c[am][an], ahi[am][0], ahi[am][1], ahi[am][2], ahi[am][3],
                             bhi[an][0], bhi[an][1]);
                    mma_tf32(c[am][an], ahi[am][0], ahi[am][1], ahi[am][2], ahi[am][3],
                             blo[an][0], blo[an][1]);
                    mma_tf32(c[am][an], alo[am][0], alo[am][1], alo[am][2], alo[am][3],
                             bhi[an][0], bhi[an][1]);
                }
        }
        __syncthreads();
    }

    #pragma unroll
    for (int an = 0; an < 4; an++) {
        const int o = bn + wn * 32 + an * 8 + 2 * tig;
        const float2 b2 = *(const float2*)&bias[o];
        #pragma unroll
        for (int am = 0; am < 2; am++) {
            const int r0 = wm * 32 + am * 16 + g;
            const int t1 = t0 + r0;
            const size_t g00 = (size_t)n * 262144 + (size_t)o * 1024 + t1;
            const size_t g01 = g00 + 1024;
            out[g00]     = c[am][an][0] + b2.x + image[g00];
            out[g01]     = c[am][an][1] + b2.y + image[g01];
            out[g00 + 8] = c[am][an][2] + b2.x + image[g00 + 8];
            out[g01 + 8] = c[am][an][3] + b2.y + image[g01 + 8];
        }
    }
}

// ---------------------------------------------------------------------------
extern "C" void kernel_launch(void* const* d_in, const int* in_sizes, int n_in,
                              void* d_out, int out_size) {
    const float* image = (const float*)d_in[0];
    const float* w_kqv = (const float*)d_in[1];
    const float* b_kqv = (const float*)d_in[2];
    const float* w_mix = (const float*)d_in[3];
    const float* b_mix = (const float*)d_in[4];
    float* out = (float*)d_out;

    cudaFuncSetAttribute(attn_tc, cudaFuncAttributeMaxDynamicSharedMemorySize,
                         ATT_SMEM);

    dim3 gridA(768 / 64, 8192 / 128);
    kqv_mma<<<gridA, 256>>>(image, w_kqv, b_kqv);

    dim3 gridB(36, 64);
    attn_tc<<<gridB, 256, ATT_SMEM>>>();

    attn_inv<<<256, 256>>>();
    attn_reduce2<<<8192, 256>>>();

    dim3 gridC(256 / 64, 8192 / 128);
    mix_mma<<<gridC, 256>>>(image, w_mix, b_mix, out);
}

// round 14
// speedup vs baseline: 1.3368x; 1.0394x over previous
#include <cuda_runtime.h>
#include <math.h>

// Problem constants
#define NBATCH 8
#define CCH    256
#define TSEQ   1024
#define NHEAD  8
#define HDIM   32

// ---- tf32 mma primitives ----
__device__ __forceinline__ unsigned tf32_of(float x) {
    unsigned r; asm("cvt.rna.tf32.f32 %0, %1;" : "=r"(r) : "f"(x)); return r;
}
__device__ __forceinline__ void tf32_split(float v, unsigned& hi, unsigned& lo) {
    hi = tf32_of(v);
    lo = tf32_of(v - __uint_as_float(hi));
}
__device__ __forceinline__ void mma_tf32(float c[4],
                                         unsigned a0, unsigned a1, unsigned a2, unsigned a3,
                                         unsigned b0, unsigned b1) {
    asm("mma.sync.aligned.m16n8k8.row.col.f32.tf32.tf32.f32 "
        "{%0,%1,%2,%3}, {%4,%5,%6,%7}, {%8,%9}, {%0,%1,%2,%3};"
        : "+f"(c[0]), "+f"(c[1]), "+f"(c[2]), "+f"(c[3])
        : "r"(a0), "r"(a1), "r"(a2), "r"(a3), "r"(b0), "r"(b1));
}
// split a float4 into hi/lo float4s (tf32 bit patterns as floats)
__device__ __forceinline__ void split4(float4 v, float4& vh, float4& vl) {
    unsigned h, l;
    tf32_split(v.x, h, l); vh.x = __uint_as_float(h); vl.x = __uint_as_float(l);
    tf32_split(v.y, h, l); vh.y = __uint_as_float(h); vl.y = __uint_as_float(l);
    tf32_split(v.z, h, l); vh.z = __uint_as_float(h); vl.z = __uint_as_float(l);
    tf32_split(v.w, h, l); vh.w = __uint_as_float(h); vl.w = __uint_as_float(l);
}

// Scratch. K/Q/V in [N, H, T, D]. g_attn TRANSPOSED: [C, N*T].
__device__ float g_k[NBATCH * NHEAD * TSEQ * HDIM];
__device__ float g_q[NBATCH * NHEAD * TSEQ * HDIM];
__device__ float g_v[NBATCH * NHEAD * TSEQ * HDIM];
__device__ float g_attn[CCH * NBATCH * TSEQ];
// Split-K partials: 36 units/nh of 128 queries x 128 keys.
__device__ float g_pacc[64 * 36 * 32 * 128];
__device__ float g_plsum[64 * 36 * 128];
__device__ float g_inv[64 * 8 * 128];     // 1/lsum per (nh, qt, q)

#define AS_STRIDE 136
#define BS_STRIDE 72

// ---------------------------------------------------------------------------
// Kernel 1: KQV projection via 3xTF32 mma.sync, SMEM FILL-TIME SPLIT:
// operands pre-split into hi/lo shared arrays once per tile (identical math;
// inner loop is pure LDS + mma, no per-use cvt/sub chains).
// ---------------------------------------------------------------------------
__global__ __launch_bounds__(256) void kqv_mma(const float* __restrict__ image,
                                               const float* __restrict__ w,
                                               const float* __restrict__ bias) {
    __shared__ float Ash[16 * AS_STRIDE];
    __shared__ float Asl[16 * AS_STRIDE];
    __shared__ float Bsh[16 * BS_STRIDE];
    __shared__ float Bsl[16 * BS_STRIDE];
    const int tid = threadIdx.x;
    const int lane = tid & 31;
    const int wid = tid >> 5;
    const int wm = wid & 3;
    const int wn = wid >> 2;
    const int g = lane >> 2, tig = lane & 3;
    const int bm = blockIdx.y * 128;
    const int bn = blockIdx.x * 64;
    const int n  = bm >> 10;
    const int t0 = bm & 1023;

    float c[2][4][4];
    #pragma unroll
    for (int am = 0; am < 2; am++)
        #pragma unroll
        for (int an = 0; an < 4; an++)
            #pragma unroll
            for (int i = 0; i < 4; i++) c[am][an][i] = 0.0f;

    float4 pa[2], pb;
    {
        #pragma unroll
        for (int l = 0; l < 2; l++) {
            int idx = l * 256 + tid;
            int k = idx >> 5, f = idx & 31;
            pa[l] = *(const float4*)&image[n * 262144 + k * 1024 + t0 + f * 4];
        }
        int k = tid >> 4, f = tid & 15;
        pb = *(const float4*)&w[k * 768 + bn + f * 4];
    }

    for (int k0 = 0; k0 < 256; k0 += 16) {
        #pragma unroll
        for (int l = 0; l < 2; l++) {
            int idx = l * 256 + tid;
            int k = idx >> 5, f = idx & 31;
            float4 vh, vl;
            split4(pa[l], vh, vl);
            *(float4*)&Ash[k * AS_STRIDE + f * 4] = vh;
            *(float4*)&Asl[k * AS_STRIDE + f * 4] = vl;
        }
        {
            int k = tid >> 4, f = tid & 15;
            float4 vh, vl;
            split4(pb, vh, vl);
            *(float4*)&Bsh[k * BS_STRIDE + f * 4] = vh;
            *(float4*)&Bsl[k * BS_STRIDE + f * 4] = vl;
        }
        __syncthreads();
        if (k0 + 16 < 256) {
            #pragma unroll
            for (int l = 0; l < 2; l++) {
                int idx = l * 256 + tid;
                int k = idx >> 5, f = idx & 31;
                pa[l] = *(const float4*)&image[n * 262144 + (k0 + 16 + k) * 1024 + t0 + f * 4];
            }
            int k = tid >> 4, f = tid & 15;
            pb = *(const float4*)&w[(k0 + 16 + k) * 768 + bn + f * 4];
        }
        #pragma unroll
        for (int ks = 0; ks < 16; ks += 8) {
            unsigned ahi[2][4], alo[2][4], bhi[4][2], blo[4][2];
            #pragma unroll
            for (int am = 0; am < 2; am++) {
                const int mb = wm * 32 + am * 16;
                ahi[am][0] = __float_as_uint(Ash[(ks + tig) * AS_STRIDE + mb + g]);
                ahi[am][1] = __float_as_uint(Ash[(ks + tig) * AS_STRIDE + mb + g + 8]);
                ahi[am][2] = __float_as_uint(Ash[(ks + tig + 4) * AS_STRIDE + mb + g]);
                ahi[am][3] = __float_as_uint(Ash[(ks + tig + 4) * AS_STRIDE + mb + g + 8]);
                alo[am][0] = __float_as_uint(Asl[(ks + tig) * AS_STRIDE + mb + g]);
                alo[am][1] = __float_as_uint(Asl[(ks + tig) * AS_STRIDE + mb + g + 8]);
                alo[am][2] = __float_as_uint(Asl[(ks + tig + 4) * AS_STRIDE + mb + g]);
                alo[am][3] = __float_as_uint(Asl[(ks + tig + 4) * AS_STRIDE + mb + g + 8]);
            }
            #pragma unroll
            for (int an = 0; an < 4; an++) {
                const int nb = wn * 32 + an * 8;
                bhi[an][0] = __float_as_uint(Bsh[(ks + tig) * BS_STRIDE + nb + g]);
                bhi[an][1] = __float_as_uint(Bsh[(ks + tig + 4) * BS_STRIDE + nb + g]);
                blo[an][0] = __float_as_uint(Bsl[(ks + tig) * BS_STRIDE + nb + g]);
                blo[an][1] = __float_as_uint(Bsl[(ks + tig + 4) * BS_STRIDE + nb + g]);
            }
            #pragma unroll
            for (int am = 0; am < 2; am++)
                #pragma unroll
                for (int an = 0; an < 4; an++) {
                    mma_tf32(c[am][an], ahi[am][0], ahi[am][1], ahi[am][2], ahi[am][3],
                             bhi[an][0], bhi[an][1]);
                    mma_tf32(c[am][an], ahi[am][0], ahi[am][1], ahi[am][2], ahi[am][3],
                             blo[an][0], blo[an][1]);
                    mma_tf32(c[am][an], alo[am][0], alo[am][1], alo[am][2], alo[am][3],
                             bhi[an][0], bhi[an][1]);
                }
        }
        __syncthreads();
    }

    #pragma unroll
    for (int an = 0; an < 4; an++) {
        const int o = bn + wn * 32 + an * 8 + 2 * tig;
        const float2 b2 = *(const float2*)&bias[o];
        const int which = o >> 8;
        const int cc = o & 255;
        const int h = cc >> 5;
        const int d0 = cc & 31;
        float* dst = (which == 0) ? g_k : (which == 1) ? g_q : g_v;
        #pragma unroll
        for (int am = 0; am < 2; am++) {
            const int r0 = wm * 32 + am * 16 + g;
            const int t1 = t0 + r0;
            const int t2 = t1 + 8;
            float2 lo = make_float2(c[am][an][0] + b2.x, c[am][an][1] + b2.y);
            float2 hi = make_float2(c[am][an][2] + b2.x, c[am][an][3] + b2.y);
            *(float2*)&dst[((size_t)(n * NHEAD + h) * TSEQ + t1) * HDIM + d0] = lo;
            *(float2*)&dst[((size_t)(n * NHEAD + h) * TSEQ + t2) * HDIM + d0] = hi;
        }
    }
}

// ---------------------------------------------------------------------------
// Kernel 2a: TENSOR-CORE split-K causal flash attention (R13 structure).
// Change: P rounded to tf32 at epilogue; lsum sums the ROUNDED values
// (consistent normalization); PV uses 2 mma terms (Ph*Vh + Ph*Vl), no P split.
// ---------------------------------------------------------------------------
#define ATT_SMEM 110592

__global__ __launch_bounds__(256) void attn_tc() {
    extern __shared__ float sm[];
    float* Qs = sm;                 // stride 136
    float* Ks = sm + 4352;          // stride 136
    float* Vh = sm + 8704;          // stride 40
    float* Vl = sm + 13824;         // stride 40
    float* Ps = sm + 18944;         // stride 136

    int x = blockIdx.x;
    int qt = 0, ubase = 0;
    while (x >= ubase + qt + 1) { ubase += qt + 1; qt++; }
    const int p = x - ubase;
    const int nh = blockIdx.y;
    const int tid = threadIdx.x;
    const int lane = tid & 31;
    const int wm = tid >> 5;
    const int g = lane >> 2, tig = lane & 3;
    const int bq = qt * 128;

    // ---- fills ----
    {   // Q, scale folded in
        const int q = tid >> 1, dh = (tid & 1) * 16;
        const float* src = g_q + ((size_t)nh * TSEQ + bq + q) * HDIM + dh;
        const float sc = 0.17677669529663687f;
        #pragma unroll
        for (int i = 0; i < 4; i++) {
            float4 v = *(const float4*)(src + i * 4);
            Qs[(dh + i * 4 + 0) * 136 + q] = v.x * sc;
            Qs[(dh + i * 4 + 1) * 136 + q] = v.y * sc;
            Qs[(dh + i * 4 + 2) * 136 + q] = v.z * sc;
            Qs[(dh + i * 4 + 3) * 136 + q] = v.w * sc;
        }
    }
    {   // K
        const int k = tid >> 1, dh = (tid & 1) * 16;
        const float* src = g_k + ((size_t)nh * TSEQ + p * 128 + k) * HDIM + dh;
        #pragma unroll
        for (int i = 0; i < 4; i++) {
            float4 v = *(const float4*)(src + i * 4);
            Ks[(dh + i * 4 + 0) * 136 + k] = v.x;
            Ks[(dh + i * 4 + 1) * 136 + k] = v.y;
            Ks[(dh + i * 4 + 2) * 136 + k] = v.z;
            Ks[(dh + i * 4 + 3) * 136 + k] = v.w;
        }
    }
    {   // V: split hi/lo
        const int k = tid >> 1, dh = (tid & 1) * 16;
        const float* src = g_v + ((size_t)nh * TSEQ + p * 128 + k) * HDIM + dh;
        #pragma unroll
        for (int i = 0; i < 4; i++) {
            float4 v = *(const float4*)(src + i * 4);
            float4 vh, vl;
            split4(v, vh, vl);
            *(float4*)&Vh[k * 40 + dh + i * 4] = vh;
            *(float4*)&Vl[k * 40 + dh + i * 4] = vl;
        }
    }
    __syncthreads();

    float o_acc[4][4];
    #pragma unroll
    for (int an = 0; an < 4; an++)
        #pragma unroll
        for (int i = 0; i < 4; i++) o_acc[an][i] = 0.0f;
    float ls0 = 0.0f, ls1 = 0.0f;

    const int mq = wm * 16;
    const int q0 = bq + mq + g;
    const bool diag = (p == qt);

    #pragma unroll
    for (int chunk = 0; chunk < 2; chunk++) {
        const int ck = chunk * 64;

        // ---- QK^T (full 3-term precision — feeds exp) ----
        float s[8][4];
        #pragma unroll
        for (int an = 0; an < 8; an++)
            #pragma unroll
            for (int i = 0; i < 4; i++) s[an][i] = 0.0f;

        #pragma unroll
        for (int ks = 0; ks < 4; ks++) {
            const int kr0 = ks * 8 + tig, kr1 = kr0 + 4;
            unsigned ah[4], al[4];
            tf32_split(Qs[kr0 * 136 + mq + g],     ah[0], al[0]);
            tf32_split(Qs[kr0 * 136 + mq + g + 8], ah[1], al[1]);
            tf32_split(Qs[kr1 * 136 + mq + g],     ah[2], al[2]);
            tf32_split(Qs[kr1 * 136 + mq + g + 8], ah[3], al[3]);
            #pragma unroll
            for (int an = 0; an < 8; an++) {
                unsigned bh0, bl0, bh1, bl1;
                tf32_split(Ks[kr0 * 136 + ck + an * 8 + g], bh0, bl0);
                tf32_split(Ks[kr1 * 136 + ck + an * 8 + g], bh1, bl1);
                mma_tf32(s[an], ah[0], ah[1], ah[2], ah[3], bh0, bh1);
                mma_tf32(s[an], ah[0], ah[1], ah[2], ah[3], bl0, bl1);
                mma_tf32(s[an], al[0], al[1], al[2], al[3], bh0, bh1);
            }
        }

        // ---- epilogue: exp -> tf32-round -> mask -> lsum(rounded) -> Ps ----
        #pragma unroll
        for (int an = 0; an < 8; an++) {
            float e0 = __uint_as_float(tf32_of(__expf(s[an][0])));
            float e1 = __uint_as_float(tf32_of(__expf(s[an][1])));
            float e2 = __uint_as_float(tf32_of(__expf(s[an][2])));
            float e3 = __uint_as_float(tf32_of(__expf(s[an][3])));
            if (diag) {
                const int key0 = p * 128 + ck + an * 8 + 2 * tig;
                if (key0     > q0)     e0 = 0.0f;
                if (key0 + 1 > q0)     e1 = 0.0f;
                if (key0     > q0 + 8) e2 = 0.0f;
                if (key0 + 1 > q0 + 8) e3 = 0.0f;
            }
            ls0 += e0 + e1;
            ls1 += e2 + e3;
            const int kl = an * 8 + 2 * tig;
            Ps[(kl    ) * 136 + mq + g    ] = e0;
            Ps[(kl + 1) * 136 + mq + g    ] = e1;
            Ps[(kl    ) * 136 + mq + g + 8] = e2;
            Ps[(kl + 1) * 136 + mq + g + 8] = e3;
        }
        __syncwarp();

        // ---- PV: O += P * V, P already tf32 (2 mma terms, no split) ----
        #pragma unroll
        for (int ks = 0; ks < 8; ks++) {
            const int kr0 = ks * 8 + tig, kr1 = kr0 + 4;
            unsigned ph[4];
            ph[0] = __float_as_uint(Ps[kr0 * 136 + mq + g]);
            ph[1] = __float_as_uint(Ps[kr0 * 136 + mq + g + 8]);
            ph[2] = __float_as_uint(Ps[kr1 * 136 + mq + g]);
            ph[3] = __float_as_uint(Ps[kr1 * 136 + mq + g + 8]);
            const int vr0 = ck + kr0, vr1 = ck + kr1;
            #pragma unroll
            for (int an = 0; an < 4; an++) {
                unsigned bh0 = __float_as_uint(Vh[vr0 * 40 + an * 8 + g]);
                unsigned bh1 = __float_as_uint(Vh[vr1 * 40 + an * 8 + g]);
                unsigned bl0 = __float_as_uint(Vl[vr0 * 40 + an * 8 + g]);
                unsigned bl1 = __float_as_uint(Vl[vr1 * 40 + an * 8 + g]);
                mma_tf32(o_acc[an], ph[0], ph[1], ph[2], ph[3], bh0, bh1);
                mma_tf32(o_acc[an], ph[0], ph[1], ph[2], ph[3], bl0, bl1);
            }
        }
        __syncwarp();
    }

    // ---- write partials ----
    float* pout = g_pacc + ((size_t)(nh * 36 + blockIdx.x) * 32) * 128;
    #pragma unroll
    for (int an = 0; an < 4; an++) {
        const int d0 = an * 8 + 2 * tig;
        const int ql = mq + g;
        pout[(d0    ) * 128 + ql    ] = o_acc[an][0];
        pout[(d0 + 1) * 128 + ql    ] = o_acc[an][1];
        pout[(d0    ) * 128 + ql + 8] = o_acc[an][2];
        pout[(d0 + 1) * 128 + ql + 8] = o_acc[an][3];
    }
    ls0 += __shfl_xor_sync(0xFFFFFFFF, ls0, 1);
    ls0 += __shfl_xor_sync(0xFFFFFFFF, ls0, 2);
    ls1 += __shfl_xor_sync(0xFFFFFFFF, ls1, 1);
    ls1 += __shfl_xor_sync(0xFFFFFFFF, ls1, 2);
    if (tig == 0) {
        float* lout = g_plsum + (size_t)(nh * 36 + blockIdx.x) * 128;
        lout[mq + g]     = ls0;
        lout[mq + g + 8] = ls1;
    }
}

// ---------------------------------------------------------------------------
// Kernel 2b: per-query inverse lsum (R11-proven).
// ---------------------------------------------------------------------------
__global__ __launch_bounds__(256) void attn_inv() {
    const int t = blockIdx.x * 256 + threadIdx.x;
    const int q  = t & 127;
    const int qt = (t >> 7) & 7;
    const int nh = t >> 10;
    const int base = qt * (qt + 1) / 2;

    float lsum = 0.0f;
    for (int p = 0; p <= qt; p++)
        lsum += g_plsum[(size_t)(nh * 36 + base + p) * 128 + q];
    g_inv[t] = 1.0f / lsum;
}

// ---------------------------------------------------------------------------
// Kernel 2c: element-parallel reduce -> g_attn [C, N*T] (R11-proven).
// ---------------------------------------------------------------------------
__global__ __launch_bounds__(256) void attn_reduce2() {
    const int t = blockIdx.x * 256 + threadIdx.x;
    const int q  = t & 127;
    const int d  = (t >> 7) & 31;
    const int qt = (t >> 12) & 7;
    const int nh = t >> 15;
    const int base = qt * (qt + 1) / 2;

    float acc = 0.0f;
    const float* pin = g_pacc + ((size_t)(nh * 36 + base) * 32 + d) * 128 + q;
    #pragma unroll 4
    for (int p = 0; p <= qt; p++)
        acc += pin[(size_t)p * 32 * 128];

    const float inv = g_inv[(nh * 8 + qt) * 128 + q];
    const int n = nh >> 3;
    const int h = nh & 7;
    const int tq = qt * 128 + q;
    g_attn[(size_t)(h * HDIM + d) * (NBATCH * TSEQ) + (size_t)n * TSEQ + tq] = acc * inv;
}

// ---------------------------------------------------------------------------
// Kernel 3: mix + bias + residual, SMEM FILL-TIME SPLIT (same as kqv).
// ---------------------------------------------------------------------------
__global__ __launch_bounds__(256) void mix_mma(const float* __restrict__ image,
                                               const float* __restrict__ w,
                                               const float* __restrict__ bias,
                                               float* __restrict__ out) {
    __shared__ float Ash[16 * AS_STRIDE];
    __shared__ float Asl[16 * AS_STRIDE];
    __shared__ float Bsh[16 * BS_STRIDE];
    __shared__ float Bsl[16 * BS_STRIDE];
    const int tid = threadIdx.x;
    const int lane = tid & 31;
    const int wid = tid >> 5;
    const int wm = wid & 3;
    const int wn = wid >> 2;
    const int g = lane >> 2, tig = lane & 3;
    const int bm = blockIdx.y * 128;
    const int bn = blockIdx.x * 64;
    const int n  = bm >> 10;
    const int t0 = bm & 1023;

    float c[2][4][4];
    #pragma unroll
    for (int am = 0; am < 2; am++)
        #pragma unroll
        for (int an = 0; an < 4; an++)
            #pragma unroll
            for (int i = 0; i < 4; i++) c[am][an][i] = 0.0f;

    float4 pa[2], pb;
    {
        #pragma unroll
        for (int l = 0; l < 2; l++) {
            int idx = l * 256 + tid;
            int k = idx >> 5, f = idx & 31;
            pa[l] = *(const float4*)&g_attn[(size_t)k * 8192 + bm + f * 4];
        }
        int k = tid >> 4, f = tid & 15;
        pb = *(const float4*)&w[k * 256 + bn + f * 4];
    }

    for (int k0 = 0; k0 < 256; k0 += 16) {
        #pragma unroll
        for (int l = 0; l < 2; l++) {
            int idx = l * 256 + tid;
            int k = idx >> 5, f = idx & 31;
            float4 vh, vl;
            split4(pa[l], vh, vl);
            *(float4*)&Ash[k * AS_STRIDE + f * 4] = vh;
            *(float4*)&Asl[k * AS_STRIDE + f * 4] = vl;
        }
        {
            int k = tid >> 4, f = tid & 15;
            float4 vh, vl;
            split4(pb, vh, vl);
            *(float4*)&Bsh[k * BS_STRIDE + f * 4] = vh;
            *(float4*)&Bsl[k * BS_STRIDE + f * 4] = vl;
        }
        __syncthreads();
        if (k0 + 16 < 256) {
            #pragma unroll
            for (int l = 0; l < 2; l++) {
                int idx = l * 256 + tid;
                int k = idx >> 5, f = idx & 31;
                pa[l] = *(const float4*)&g_attn[(size_t)(k0 + 16 + k) * 8192 + bm + f * 4];
            }
            int k = tid >> 4, f = tid & 15;
            pb = *(const float4*)&w[(k0 + 16 + k) * 256 + bn + f * 4];
        }
        #pragma unroll
        for (int ks = 0; ks < 16; ks += 8) {
            unsigned ahi[2][4], alo[2][4], bhi[4][2], blo[4][2];
            #pragma unroll
            for (int am = 0; am < 2; am++) {
                const int mb = wm * 32 + am * 16;
                ahi[am][0] = __float_as_uint(Ash[(ks + tig) * AS_STRIDE + mb + g]);
                ahi[am][1] = __float_as_uint(Ash[(ks + tig) * AS_STRIDE + mb + g + 8]);
                ahi[am][2] = __float_as_uint(Ash[(ks + tig + 4) * AS_STRIDE + mb + g]);
                ahi[am][3] = __float_as_uint(Ash[(ks + tig + 4) * AS_STRIDE + mb + g + 8]);
                alo[am][0] = __float_as_uint(Asl[(ks + tig) * AS_STRIDE + mb + g]);
                alo[am][1] = __float_as_uint(Asl[(ks + tig) * AS_STRIDE + mb + g + 8]);
                alo[am][2] = __float_as_uint(Asl[(ks + tig + 4) * AS_STRIDE + mb + g]);
                alo[am][3] = __float_as_uint(Asl[(ks + tig + 4) * AS_STRIDE + mb + g + 8]);
            }
            #pragma unroll
            for (int an = 0; an < 4; an++) {
                const int nb = wn * 32 + an * 8;
                bhi[an][0] = __float_as_uint(Bsh[(ks + tig) * BS_STRIDE + nb + g]);
                bhi[an][1] = __float_as_uint(Bsh[(ks + tig + 4) * BS_STRIDE + nb + g]);
                blo[an][0] = __float_as_uint(Bsl[(ks + tig) * BS_STRIDE + nb + g]);
                blo[an][1] = __float_as_uint(Bsl[(ks + tig + 4) * BS_STRIDE + nb + g]);
            }
            #pragma unroll
            for (int am = 0; am < 2; am++)
                #pragma unroll
                for (int an = 0; an < 4; an++) {
                    mma_tf32(c[am][an], ahi[am][0], ahi[am][1], ahi[am][2], ahi[am][3],
                             bhi[an][0], bhi[an][1]);
                    mma_tf32(c[am][an], ahi[am][0], ahi[am][1], ahi[am][2], ahi[am][3],
                             blo[an][0], blo[an][1]);
                    mma_tf32(c[am][an], alo[am][0], alo[am][1], alo[am][2], alo[am][3],
                             bhi[an][0], bhi[an][1]);
                }
        }
        __syncthreads();
    }

    #pragma unroll
    for (int an = 0; an < 4; an++) {
        const int o = bn + wn * 32 + an * 8 + 2 * tig;
        const float2 b2 = *(const float2*)&bias[o];
        #pragma unroll
        for (int am = 0; am < 2; am++) {
            const int r0 = wm * 32 + am * 16 + g;
            const int t1 = t0 + r0;
            const size_t g00 = (size_t)n * 262144 + (size_t)o * 1024 + t1;
            const size_t g01 = g00 + 1024;
            out[g00]     = c[am][an][0] + b2.x + image[g00];
            out[g01]     = c[am][an][1] + b2.y + image[g01];
            out[g00 + 8] = c[am][an][2] + b2.x + image[g00 + 8];
            out[g01 + 8] = c[am][an][3] + b2.y + image[g01 + 8];
        }
    }
}

// ---------------------------------------------------------------------------
extern "C" void kernel_launch(void* const* d_in, const int* in_sizes, int n_in,
                              void* d_out, int out_size) {
    const float* image = (const float*)d_in[0];
    const float* w_kqv = (const float*)d_in[1];
    const float* b_kqv = (const float*)d_in[2];
    const float* w_mix = (const float*)d_in[3];
    const float* b_mix = (const float*)d_in[4];
    float* out = (float*)d_out;

    cudaFuncSetAttribute(attn_tc, cudaFuncAttributeMaxDynamicSharedMemorySize,
                         ATT_SMEM);

    dim3 gridA(768 / 64, 8192 / 128);
    kqv_mma<<<gridA, 256>>>(image, w_kqv, b_kqv);

    dim3 gridB(36, 64);
    attn_tc<<<gridB, 256, ATT_SMEM>>>();

    attn_inv<<<256, 256>>>();
    attn_reduce2<<<8192, 256>>>();

    dim3 gridC(256 / 64, 8192 / 128);
    mix_mma<<<gridC, 256>>>(image, w_mix, b_mix, out);
}

// round 15
// speedup vs baseline: 2.0127x; 1.5055x over previous
#include <cuda_runtime.h>
#include <math.h>

// Problem constants
#define NBATCH 8
#define CCH    256
#define TSEQ   1024
#define NHEAD  8
#define HDIM   32

// ---- tf32 mma primitives ----
__device__ __forceinline__ unsigned tf32_of(float x) {
    unsigned r; asm("cvt.rna.tf32.f32 %0, %1;" : "=r"(r) : "f"(x)); return r;
}
__device__ __forceinline__ float tf32f(float x) {
    return __uint_as_float(tf32_of(x));
}
__device__ __forceinline__ void tf32_split(float v, unsigned& hi, unsigned& lo) {
    hi = tf32_of(v);
    lo = tf32_of(v - __uint_as_float(hi));
}
__device__ __forceinline__ void mma_tf32(float c[4],
                                         unsigned a0, unsigned a1, unsigned a2, unsigned a3,
                                         unsigned b0, unsigned b1) {
    asm("mma.sync.aligned.m16n8k8.row.col.f32.tf32.tf32.f32 "
        "{%0,%1,%2,%3}, {%4,%5,%6,%7}, {%8,%9}, {%0,%1,%2,%3};"
        : "+f"(c[0]), "+f"(c[1]), "+f"(c[2]), "+f"(c[3])
        : "r"(a0), "r"(a1), "r"(a2), "r"(a3), "r"(b0), "r"(b1));
}
// split a float4 into hi/lo float4s (tf32 bit patterns as floats)
__device__ __forceinline__ void split4(float4 v, float4& vh, float4& vl) {
    unsigned h, l;
    tf32_split(v.x, h, l); vh.x = __uint_as_float(h); vl.x = __uint_as_float(l);
    tf32_split(v.y, h, l); vh.y = __uint_as_float(h); vl.y = __uint_as_float(l);
    tf32_split(v.z, h, l); vh.z = __uint_as_float(h); vl.z = __uint_as_float(l);
    tf32_split(v.w, h, l); vh.w = __uint_as_float(h); vl.w = __uint_as_float(l);
}
// round a float4 to tf32 bit patterns (as floats)
__device__ __forceinline__ float4 round4(float4 v) {
    return make_float4(tf32f(v.x), tf32f(v.y), tf32f(v.z), tf32f(v.w));
}

// Scratch. K/Q/V in [N, H, T, D]. g_attn TRANSPOSED: [C, N*T].
__device__ float g_k[NBATCH * NHEAD * TSEQ * HDIM];
__device__ float g_q[NBATCH * NHEAD * TSEQ * HDIM];
__device__ float g_v[NBATCH * NHEAD * TSEQ * HDIM];
__device__ float g_attn[CCH * NBATCH * TSEQ];
// Split-K partials: 36 units/nh of 128 queries x 128 keys.
__device__ float g_pacc[64 * 36 * 32 * 128];
__device__ float g_plsum[64 * 36 * 128];
__device__ float g_inv[64 * 8 * 128];     // 1/lsum per (nh, qt, q)

#define AS_STRIDE 136
#define BS_STRIDE 72

// ---------------------------------------------------------------------------
// Kernel 1: KQV projection, SINGLE-TERM tf32 mma (inputs rounded at fill).
// Error from rounding averages through downstream softmax (see R15 theory);
// bias added in fp32.
// ---------------------------------------------------------------------------
__global__ __launch_bounds__(256) void kqv_mma(const float* __restrict__ image,
                                               const float* __restrict__ w,
                                               const float* __restrict__ bias) {
    __shared__ float As[16 * AS_STRIDE];
    __shared__ float Bs[16 * BS_STRIDE];
    const int tid = threadIdx.x;
    const int lane = tid & 31;
    const int wid = tid >> 5;
    const int wm = wid & 3;
    const int wn = wid >> 2;
    const int g = lane >> 2, tig = lane & 3;
    const int bm = blockIdx.y * 128;
    const int bn = blockIdx.x * 64;
    const int n  = bm >> 10;
    const int t0 = bm & 1023;

    float c[2][4][4];
    #pragma unroll
    for (int am = 0; am < 2; am++)
        #pragma unroll
        for (int an = 0; an < 4; an++)
            #pragma unroll
            for (int i = 0; i < 4; i++) c[am][an][i] = 0.0f;

    float4 pa[2], pb;
    {
        #pragma unroll
        for (int l = 0; l < 2; l++) {
            int idx = l * 256 + tid;
            int k = idx >> 5, f = idx & 31;
            pa[l] = *(const float4*)&image[n * 262144 + k * 1024 + t0 + f * 4];
        }
        int k = tid >> 4, f = tid & 15;
        pb = *(const float4*)&w[k * 768 + bn + f * 4];
    }

    for (int k0 = 0; k0 < 256; k0 += 16) {
        #pragma unroll
        for (int l = 0; l < 2; l++) {
            int idx = l * 256 + tid;
            int k = idx >> 5, f = idx & 31;
            *(float4*)&As[k * AS_STRIDE + f * 4] = round4(pa[l]);
        }
        {
            int k = tid >> 4, f = tid & 15;
            *(float4*)&Bs[k * BS_STRIDE + f * 4] = round4(pb);
        }
        __syncthreads();
        if (k0 + 16 < 256) {
            #pragma unroll
            for (int l = 0; l < 2; l++) {
                int idx = l * 256 + tid;
                int k = idx >> 5, f = idx & 31;
                pa[l] = *(const float4*)&image[n * 262144 + (k0 + 16 + k) * 1024 + t0 + f * 4];
            }
            int k = tid >> 4, f = tid & 15;
            pb = *(const float4*)&w[(k0 + 16 + k) * 768 + bn + f * 4];
        }
        #pragma unroll
        for (int ks = 0; ks < 16; ks += 8) {
            unsigned a[2][4], b[4][2];
            #pragma unroll
            for (int am = 0; am < 2; am++) {
                const int mb = wm * 32 + am * 16;
                a[am][0] = __float_as_uint(As[(ks + tig) * AS_STRIDE + mb + g]);
                a[am][1] = __float_as_uint(As[(ks + tig) * AS_STRIDE + mb + g + 8]);
                a[am][2] = __float_as_uint(As[(ks + tig + 4) * AS_STRIDE + mb + g]);
                a[am][3] = __float_as_uint(As[(ks + tig + 4) * AS_STRIDE + mb + g + 8]);
            }
            #pragma unroll
            for (int an = 0; an < 4; an++) {
                const int nb = wn * 32 + an * 8;
                b[an][0] = __float_as_uint(Bs[(ks + tig) * BS_STRIDE + nb + g]);
                b[an][1] = __float_as_uint(Bs[(ks + tig + 4) * BS_STRIDE + nb + g]);
            }
            #pragma unroll
            for (int am = 0; am < 2; am++)
                #pragma unroll
                for (int an = 0; an < 4; an++)
                    mma_tf32(c[am][an], a[am][0], a[am][1], a[am][2], a[am][3],
                             b[an][0], b[an][1]);
        }
        __syncthreads();
    }

    #pragma unroll
    for (int an = 0; an < 4; an++) {
        const int o = bn + wn * 32 + an * 8 + 2 * tig;
        const float2 b2 = *(const float2*)&bias[o];
        const int which = o >> 8;
        const int cc = o & 255;
        const int h = cc >> 5;
        const int d0 = cc & 31;
        float* dst = (which == 0) ? g_k : (which == 1) ? g_q : g_v;
        #pragma unroll
        for (int am = 0; am < 2; am++) {
            const int r0 = wm * 32 + am * 16 + g;
            const int t1 = t0 + r0;
            const int t2 = t1 + 8;
            float2 lo = make_float2(c[am][an][0] + b2.x, c[am][an][1] + b2.y);
            float2 hi = make_float2(c[am][an][2] + b2.x, c[am][an][3] + b2.y);
            *(float2*)&dst[((size_t)(n * NHEAD + h) * TSEQ + t1) * HDIM + d0] = lo;
            *(float2*)&dst[((size_t)(n * NHEAD + h) * TSEQ + t2) * HDIM + d0] = hi;
        }
    }
}

// ---------------------------------------------------------------------------
// Kernel 2a: TENSOR-CORE split-K causal flash attention, FULL tf32:
// Q/K/V rounded to tf32 at smem fill; QK^T and PV single-term mma.
// P rounded to tf32, lsum sums rounded values (consistent normalization).
// Smem (floats): Qs[32][136]@0, Ks[32][136]@4352, Vs[128][40]@8704,
//                Ps[64][136]@13824  -> 22528 floats = 90112 B.
// ---------------------------------------------------------------------------
#define ATT_SMEM 90112

__global__ __launch_bounds__(256) void attn_tc() {
    extern __shared__ float sm[];
    float* Qs = sm;                 // stride 136
    float* Ks = sm + 4352;          // stride 136
    float* Vs = sm + 8704;          // stride 40
    float* Ps = sm + 13824;         // stride 136

    int x = blockIdx.x;
    int qt = 0, ubase = 0;
    while (x >= ubase + qt + 1) { ubase += qt + 1; qt++; }
    const int p = x - ubase;
    const int nh = blockIdx.y;
    const int tid = threadIdx.x;
    const int lane = tid & 31;
    const int wm = tid >> 5;
    const int g = lane >> 2, tig = lane & 3;
    const int bq = qt * 128;

    // ---- fills (rounded to tf32) ----
    {   // Q, scale folded in then rounded
        const int q = tid >> 1, dh = (tid & 1) * 16;
        const float* src = g_q + ((size_t)nh * TSEQ + bq + q) * HDIM + dh;
        const float sc = 0.17677669529663687f;
        #pragma unroll
        for (int i = 0; i < 4; i++) {
            float4 v = *(const float4*)(src + i * 4);
            Qs[(dh + i * 4 + 0) * 136 + q] = tf32f(v.x * sc);
            Qs[(dh + i * 4 + 1) * 136 + q] = tf32f(v.y * sc);
            Qs[(dh + i * 4 + 2) * 136 + q] = tf32f(v.z * sc);
            Qs[(dh + i * 4 + 3) * 136 + q] = tf32f(v.w * sc);
        }
    }
    {   // K rounded
        const int k = tid >> 1, dh = (tid & 1) * 16;
        const float* src = g_k + ((size_t)nh * TSEQ + p * 128 + k) * HDIM + dh;
        #pragma unroll
        for (int i = 0; i < 4; i++) {
            float4 v = *(const float4*)(src + i * 4);
            Ks[(dh + i * 4 + 0) * 136 + k] = tf32f(v.x);
            Ks[(dh + i * 4 + 1) * 136 + k] = tf32f(v.y);
            Ks[(dh + i * 4 + 2) * 136 + k] = tf32f(v.z);
            Ks[(dh + i * 4 + 3) * 136 + k] = tf32f(v.w);
        }
    }
    {   // V rounded, [key][d] stride 40
        const int k = tid >> 1, dh = (tid & 1) * 16;
        const float* src = g_v + ((size_t)nh * TSEQ + p * 128 + k) * HDIM + dh;
        #pragma unroll
        for (int i = 0; i < 4; i++) {
            float4 v = *(const float4*)(src + i * 4);
            *(float4*)&Vs[k * 40 + dh + i * 4] = round4(v);
        }
    }
    __syncthreads();

    float o_acc[4][4];
    #pragma unroll
    for (int an = 0; an < 4; an++)
        #pragma unroll
        for (int i = 0; i < 4; i++) o_acc[an][i] = 0.0f;
    float ls0 = 0.0f, ls1 = 0.0f;

    const int mq = wm * 16;
    const int q0 = bq + mq + g;
    const bool diag = (p == qt);

    #pragma unroll
    for (int chunk = 0; chunk < 2; chunk++) {
        const int ck = chunk * 64;

        // ---- QK^T: single-term tf32 ----
        float s[8][4];
        #pragma unroll
        for (int an = 0; an < 8; an++)
            #pragma unroll
            for (int i = 0; i < 4; i++) s[an][i] = 0.0f;

        #pragma unroll
        for (int ks = 0; ks < 4; ks++) {
            const int kr0 = ks * 8 + tig, kr1 = kr0 + 4;
            unsigned a[4];
            a[0] = __float_as_uint(Qs[kr0 * 136 + mq + g]);
            a[1] = __float_as_uint(Qs[kr0 * 136 + mq + g + 8]);
            a[2] = __float_as_uint(Qs[kr1 * 136 + mq + g]);
            a[3] = __float_as_uint(Qs[kr1 * 136 + mq + g + 8]);
            #pragma unroll
            for (int an = 0; an < 8; an++) {
                unsigned b0 = __float_as_uint(Ks[kr0 * 136 + ck + an * 8 + g]);
                unsigned b1 = __float_as_uint(Ks[kr1 * 136 + ck + an * 8 + g]);
                mma_tf32(s[an], a[0], a[1], a[2], a[3], b0, b1);
            }
        }

        // ---- epilogue: exp -> tf32-round -> mask -> lsum(rounded) -> Ps ----
        #pragma unroll
        for (int an = 0; an < 8; an++) {
            float e0 = tf32f(__expf(s[an][0]));
            float e1 = tf32f(__expf(s[an][1]));
            float e2 = tf32f(__expf(s[an][2]));
            float e3 = tf32f(__expf(s[an][3]));
            if (diag) {
                const int key0 = p * 128 + ck + an * 8 + 2 * tig;
                if (key0     > q0)     e0 = 0.0f;
                if (key0 + 1 > q0)     e1 = 0.0f;
                if (key0     > q0 + 8) e2 = 0.0f;
                if (key0 + 1 > q0 + 8) e3 = 0.0f;
            }
            ls0 += e0 + e1;
            ls1 += e2 + e3;
            const int kl = an * 8 + 2 * tig;
            Ps[(kl    ) * 136 + mq + g    ] = e0;
            Ps[(kl + 1) * 136 + mq + g    ] = e1;
            Ps[(kl    ) * 136 + mq + g + 8] = e2;
            Ps[(kl + 1) * 136 + mq + g + 8] = e3;
        }
        __syncwarp();

        // ---- PV: single-term tf32 (P and V both pre-rounded) ----
        #pragma unroll
        for (int ks = 0; ks < 8; ks++) {
            const int kr0 = ks * 8 + tig, kr1 = kr0 + 4;
            unsigned ph[4];
            ph[0] = __float_as_uint(Ps[kr0 * 136 + mq + g]);
            ph[1] = __float_as_uint(Ps[kr0 * 136 + mq + g + 8]);
            ph[2] = __float_as_uint(Ps[kr1 * 136 + mq + g]);
            ph[3] = __float_as_uint(Ps[kr1 * 136 + mq + g + 8]);
            const int vr0 = ck + kr0, vr1 = ck + kr1;
            #pragma unroll
            for (int an = 0; an < 4; an++) {
                unsigned b0 = __float_as_uint(Vs[vr0 * 40 + an * 8 + g]);
                unsigned b1 = __float_as_uint(Vs[vr1 * 40 + an * 8 + g]);
                mma_tf32(o_acc[an], ph[0], ph[1], ph[2], ph[3], b0, b1);
            }
        }
        __syncwarp();
    }

    // ---- write partials ----
    float* pout = g_pacc + ((size_t)(nh * 36 + blockIdx.x) * 32) * 128;
    #pragma unroll
    for (int an = 0; an < 4; an++) {
        const int d0 = an * 8 + 2 * tig;
        const int ql = mq + g;
        pout[(d0    ) * 128 + ql    ] = o_acc[an][0];
        pout[(d0 + 1) * 128 + ql    ] = o_acc[an][1];
        pout[(d0    ) * 128 + ql + 8] = o_acc[an][2];
        pout[(d0 + 1) * 128 + ql + 8] = o_acc[an][3];
    }
    ls0 += __shfl_xor_sync(0xFFFFFFFF, ls0, 1);
    ls0 += __shfl_xor_sync(0xFFFFFFFF, ls0, 2);
    ls1 += __shfl_xor_sync(0xFFFFFFFF, ls1, 1);
    ls1 += __shfl_xor_sync(0xFFFFFFFF, ls1, 2);
    if (tig == 0) {
        float* lout = g_plsum + (size_t)(nh * 36 + blockIdx.x) * 128;
        lout[mq + g]     = ls0;
        lout[mq + g + 8] = ls1;
    }
}

// ---------------------------------------------------------------------------
// Kernel 2b: per-query inverse lsum (R11-proven).
// ---------------------------------------------------------------------------
__global__ __launch_bounds__(256) void attn_inv() {
    const int t = blockIdx.x * 256 + threadIdx.x;
    const int q  = t & 127;
    const int qt = (t >> 7) & 7;
    const int nh = t >> 10;
    const int base = qt * (qt + 1) / 2;

    float lsum = 0.0f;
    for (int p = 0; p <= qt; p++)
        lsum += g_plsum[(size_t)(nh * 36 + base + p) * 128 + q];
    g_inv[t] = 1.0f / lsum;
}

// ---------------------------------------------------------------------------
// Kernel 2c: element-parallel reduce -> g_attn [C, N*T] (R11-proven).
// ---------------------------------------------------------------------------
__global__ __launch_bounds__(256) void attn_reduce2() {
    const int t = blockIdx.x * 256 + threadIdx.x;
    const int q  = t & 127;
    const int d  = (t >> 7) & 31;
    const int qt = (t >> 12) & 7;
    const int nh = t >> 15;
    const int base = qt * (qt + 1) / 2;

    float acc = 0.0f;
    const float* pin = g_pacc + ((size_t)(nh * 36 + base) * 32 + d) * 128 + q;
    #pragma unroll 4
    for (int p = 0; p <= qt; p++)
        acc += pin[(size_t)p * 32 * 128];

    const float inv = g_inv[(nh * 8 + qt) * 128 + q];
    const int n = nh >> 3;
    const int h = nh & 7;
    const int tq = qt * 128 + q;
    g_attn[(size_t)(h * HDIM + d) * (NBATCH * TSEQ) + (size_t)n * TSEQ + tq] = acc * inv;
}

// ---------------------------------------------------------------------------
// Kernel 3: mix + bias + residual, 3-TERM tf32 (precision anchor — this is
// the direct, non-averaged path to the output). Fill-time split (R14).
// ---------------------------------------------------------------------------
__global__ __launch_bounds__(256) void mix_mma(const float* __restrict__ image,
                                               const float* __restrict__ w,
                                               const float* __restrict__ bias,
                                               float* __restrict__ out) {
    __shared__ float Ash[16 * AS_STRIDE];
    __shared__ float Asl[16 * AS_STRIDE];
    __shared__ float Bsh[16 * BS_STRIDE];
    __shared__ float Bsl[16 * BS_STRIDE];
    const int tid = threadIdx.x;
    const int lane = tid & 31;
    const int wid = tid >> 5;
    const int wm = wid & 3;
    const int wn = wid >> 2;
    const int g = lane >> 2, tig = lane & 3;
    const int bm = blockIdx.y * 128;
    const int bn = blockIdx.x * 64;
    const int n  = bm >> 10;
    const int t0 = bm & 1023;

    float c[2][4][4];
    #pragma unroll
    for (int am = 0; am < 2; am++)
        #pragma unroll
        for (int an = 0; an < 4; an++)
            #pragma unroll
            for (int i = 0; i < 4; i++) c[am][an][i] = 0.0f;

    float4 pa[2], pb;
    {
        #pragma unroll
        for (int l = 0; l < 2; l++) {
            int idx = l * 256 + tid;
            int k = idx >> 5, f = idx & 31;
            pa[l] = *(const float4*)&g_attn[(size_t)k * 8192 + bm + f * 4];
        }
        int k = tid >> 4, f = tid & 15;
        pb = *(const float4*)&w[k * 256 + bn + f * 4];
    }

    for (int k0 = 0; k0 < 256; k0 += 16) {
        #pragma unroll
        for (int l = 0; l < 2; l++) {
            int idx = l * 256 + tid;
            int k = idx >> 5, f = idx & 31;
            float4 vh, vl;
            split4(pa[l], vh, vl);
            *(float4*)&Ash[k * AS_STRIDE + f * 4] = vh;
            *(float4*)&Asl[k * AS_STRIDE + f * 4] = vl;
        }
        {
            int k = tid >> 4, f = tid & 15;
            float4 vh, vl;
            split4(pb, vh, vl);
            *(float4*)&Bsh[k * BS_STRIDE + f * 4] = vh;
            *(float4*)&Bsl[k * BS_STRIDE + f * 4] = vl;
        }
        __syncthreads();
        if (k0 + 16 < 256) {
            #pragma unroll
            for (int l = 0; l < 2; l++) {
                int idx = l * 256 + tid;
                int k = idx >> 5, f = idx & 31;
                pa[l] = *(const float4*)&g_attn[(size_t)(k0 + 16 + k) * 8192 + bm + f * 4];
            }
            int k = tid >> 4, f = tid & 15;
            pb = *(const float4*)&w[(k0 + 16 + k) * 256 + bn + f * 4];
        }
        #pragma unroll
        for (int ks = 0; ks < 16; ks += 8) {
            unsigned ahi[2][4], alo[2][4], bhi[4][2], blo[4][2];
            #pragma unroll
            for (int am = 0; am < 2; am++) {
                const int mb = wm * 32 + am * 16;
                ahi[am][0] = __float_as_uint(Ash[(ks + tig) * AS_STRIDE + mb + g]);
                ahi[am][1] = __float_as_uint(Ash[(ks + tig) * AS_STRIDE + mb + g + 8]);
                ahi[am][2] = __float_as_uint(Ash[(ks + tig + 4) * AS_STRIDE + mb + g]);
                ahi[am][3] = __float_as_uint(Ash[(ks + tig + 4) * AS_STRIDE + mb + g + 8]);
                alo[am][0] = __float_as_uint(Asl[(ks + tig) * AS_STRIDE + mb + g]);
                alo[am][1] = __float_as_uint(Asl[(ks + tig) * AS_STRIDE + mb + g + 8]);
                alo[am][2] = __float_as_uint(Asl[(ks + tig + 4) * AS_STRIDE + mb + g]);
                alo[am][3] = __float_as_uint(Asl[(ks + tig + 4) * AS_STRIDE + mb + g + 8]);
            }
            #pragma unroll
            for (int an = 0; an < 4; an++) {
                const int nb = wn * 32 + an * 8;
                bhi[an][0] = __float_as_uint(Bsh[(ks + tig) * BS_STRIDE + nb + g]);
                bhi[an][1] = __float_as_uint(Bsh[(ks + tig + 4) * BS_STRIDE + nb + g]);
                blo[an][0] = __float_as_uint(Bsl[(ks + tig) * BS_STRIDE + nb + g]);
                blo[an][1] = __float_as_uint(Bsl[(ks + tig + 4) * BS_STRIDE + nb + g]);
            }
            #pragma unroll
            for (int am = 0; am < 2; am++)
                #pragma unroll
                for (int an = 0; an < 4; an++) {
                    mma_tf32(c[am][an], ahi[am][0], ahi[am][1], ahi[am][2], ahi[am][3],
                             bhi[an][0], bhi[an][1]);
                    mma_tf32(c[am][an], ahi[am][0], ahi[am][1], ahi[am][2], ahi[am][3],
                             blo[an][0], blo[an][1]);
                    mma_tf32(c[am][an], alo[am][0], alo[am][1], alo[am][2], alo[am][3],
                             bhi[an][0], bhi[an][1]);
                }
        }
        __syncthreads();
    }

    #pragma unroll
    for (int an = 0; an < 4; an++) {
        const int o = bn + wn * 32 + an * 8 + 2 * tig;
        const float2 b2 = *(const float2*)&bias[o];
        #pragma unroll
        for (int am = 0; am < 2; am++) {
            const int r0 = wm * 32 + am * 16 + g;
            const int t1 = t0 + r0;
            const size_t g00 = (size_t)n * 262144 + (size_t)o * 1024 + t1;
            const size_t g01 = g00 + 1024;
            out[g00]     = c[am][an][0] + b2.x + image[g00];
            out[g01]     = c[am][an][1] + b2.y + image[g01];
            out[g00 + 8] = c[am][an][2] + b2.x + image[g00 + 8];
            out[g01 + 8] = c[am][an][3] + b2.y + image[g01 + 8];
        }
    }
}

// ---------------------------------------------------------------------------
extern "C" void kernel_launch(void* const* d_in, const int* in_sizes, int n_in,
                              void* d_out, int out_size) {
    const float* image = (const float*)d_in[0];
    const float* w_kqv = (const float*)d_in[1];
    const float* b_kqv = (const float*)d_in[2];
    const float* w_mix = (const float*)d_in[3];
    const float* b_mix = (const float*)d_in[4];
    float* out = (float*)d_out;

    cudaFuncSetAttribute(attn_tc, cudaFuncAttributeMaxDynamicSharedMemorySize,
                         ATT_SMEM);

    dim3 gridA(768 / 64, 8192 / 128);
    kqv_mma<<<gridA, 256>>>(image, w_kqv, b_kqv);

    dim3 gridB(36, 64);
    attn_tc<<<gridB, 256, ATT_SMEM>>>();

    attn_inv<<<256, 256>>>();
    attn_reduce2<<<8192, 256>>>();

    dim3 gridC(256 / 64, 8192 / 128);
    mix_mma<<<gridC, 256>>>(image, w_mix, b_mix, out);
}

// round 16
// speedup vs baseline: 2.2301x; 1.1080x over previous
#include <cuda_runtime.h>
#include <math.h>

// Problem constants
#define NBATCH 8
#define CCH    256
#define TSEQ   1024
#define NHEAD  8
#define HDIM   32

// ---- tf32 mma primitives ----
__device__ __forceinline__ unsigned tf32_of(float x) {
    unsigned r; asm("cvt.rna.tf32.f32 %0, %1;" : "=r"(r) : "f"(x)); return r;
}
__device__ __forceinline__ float tf32f(float x) {
    return __uint_as_float(tf32_of(x));
}
__device__ __forceinline__ void mma_tf32(float c[4],
                                         unsigned a0, unsigned a1, unsigned a2, unsigned a3,
                                         unsigned b0, unsigned b1) {
    asm("mma.sync.aligned.m16n8k8.row.col.f32.tf32.tf32.f32 "
        "{%0,%1,%2,%3}, {%4,%5,%6,%7}, {%8,%9}, {%0,%1,%2,%3};"
        : "+f"(c[0]), "+f"(c[1]), "+f"(c[2]), "+f"(c[3])
        : "r"(a0), "r"(a1), "r"(a2), "r"(a3), "r"(b0), "r"(b1));
}
// round a float4 to tf32 bit patterns (as floats)
__device__ __forceinline__ float4 round4(float4 v) {
    return make_float4(tf32f(v.x), tf32f(v.y), tf32f(v.z), tf32f(v.w));
}

// Scratch. K/Q/V in [N, H, T, D]. g_attn TRANSPOSED: [C, N*T].
__device__ float g_k[NBATCH * NHEAD * TSEQ * HDIM];
__device__ float g_q[NBATCH * NHEAD * TSEQ * HDIM];
__device__ float g_v[NBATCH * NHEAD * TSEQ * HDIM];
__device__ float g_attn[CCH * NBATCH * TSEQ];
// Split-K partials: 36 units/nh of 128 queries x 128 keys.
__device__ float g_pacc[64 * 36 * 32 * 128];
__device__ float g_plsum[64 * 36 * 128];
__device__ float g_inv[64 * 8 * 128];     // 1/lsum per (nh, qt, q)

#define AS_STRIDE 136
#define BS_STRIDE 72

// ---------------------------------------------------------------------------
// Kernel 1: KQV projection, single-term tf32 mma (R15-proven).
// ---------------------------------------------------------------------------
__global__ __launch_bounds__(256) void kqv_mma(const float* __restrict__ image,
                                               const float* __restrict__ w,
                                               const float* __restrict__ bias) {
    __shared__ float As[16 * AS_STRIDE];
    __shared__ float Bs[16 * BS_STRIDE];
    const int tid = threadIdx.x;
    const int lane = tid & 31;
    const int wid = tid >> 5;
    const int wm = wid & 3;
    const int wn = wid >> 2;
    const int g = lane >> 2, tig = lane & 3;
    const int bm = blockIdx.y * 128;
    const int bn = blockIdx.x * 64;
    const int n  = bm >> 10;
    const int t0 = bm & 1023;

    float c[2][4][4];
    #pragma unroll
    for (int am = 0; am < 2; am++)
        #pragma unroll
        for (int an = 0; an < 4; an++)
            #pragma unroll
            for (int i = 0; i < 4; i++) c[am][an][i] = 0.0f;

    float4 pa[2], pb;
    {
        #pragma unroll
        for (int l = 0; l < 2; l++) {
            int idx = l * 256 + tid;
            int k = idx >> 5, f = idx & 31;
            pa[l] = *(const float4*)&image[n * 262144 + k * 1024 + t0 + f * 4];
        }
        int k = tid >> 4, f = tid & 15;
        pb = *(const float4*)&w[k * 768 + bn + f * 4];
    }

    for (int k0 = 0; k0 < 256; k0 += 16) {
        #pragma unroll
        for (int l = 0; l < 2; l++) {
            int idx = l * 256 + tid;
            int k = idx >> 5, f = idx & 31;
            *(float4*)&As[k * AS_STRIDE + f * 4] = round4(pa[l]);
        }
        {
            int k = tid >> 4, f = tid & 15;
            *(float4*)&Bs[k * BS_STRIDE + f * 4] = round4(pb);
        }
        __syncthreads();
        if (k0 + 16 < 256) {
            #pragma unroll
            for (int l = 0; l < 2; l++) {
                int idx = l * 256 + tid;
                int k = idx >> 5, f = idx & 31;
                pa[l] = *(const float4*)&image[n * 262144 + (k0 + 16 + k) * 1024 + t0 + f * 4];
            }
            int k = tid >> 4, f = tid & 15;
            pb = *(const float4*)&w[(k0 + 16 + k) * 768 + bn + f * 4];
        }
        #pragma unroll
        for (int ks = 0; ks < 16; ks += 8) {
            unsigned a[2][4], b[4][2];
            #pragma unroll
            for (int am = 0; am < 2; am++) {
                const int mb = wm * 32 + am * 16;
                a[am][0] = __float_as_uint(As[(ks + tig) * AS_STRIDE + mb + g]);
                a[am][1] = __float_as_uint(As[(ks + tig) * AS_STRIDE + mb + g + 8]);
                a[am][2] = __float_as_uint(As[(ks + tig + 4) * AS_STRIDE + mb + g]);
                a[am][3] = __float_as_uint(As[(ks + tig + 4) * AS_STRIDE + mb + g + 8]);
            }
            #pragma unroll
            for (int an = 0; an < 4; an++) {
                const int nb = wn * 32 + an * 8;
                b[an][0] = __float_as_uint(Bs[(ks + tig) * BS_STRIDE + nb + g]);
                b[an][1] = __float_as_uint(Bs[(ks + tig + 4) * BS_STRIDE + nb + g]);
            }
            #pragma unroll
            for (int am = 0; am < 2; am++)
                #pragma unroll
                for (int an = 0; an < 4; an++)
                    mma_tf32(c[am][an], a[am][0], a[am][1], a[am][2], a[am][3],
                             b[an][0], b[an][1]);
        }
        __syncthreads();
    }

    #pragma unroll
    for (int an = 0; an < 4; an++) {
        const int o = bn + wn * 32 + an * 8 + 2 * tig;
        const float2 b2 = *(const float2*)&bias[o];
        const int which = o >> 8;
        const int cc = o & 255;
        const int h = cc >> 5;
        const int d0 = cc & 31;
        float* dst = (which == 0) ? g_k : (which == 1) ? g_q : g_v;
        #pragma unroll
        for (int am = 0; am < 2; am++) {
            const int r0 = wm * 32 + am * 16 + g;
            const int t1 = t0 + r0;
            const int t2 = t1 + 8;
            float2 lo = make_float2(c[am][an][0] + b2.x, c[am][an][1] + b2.y);
            float2 hi = make_float2(c[am][an][2] + b2.x, c[am][an][3] + b2.y);
            *(float2*)&dst[((size_t)(n * NHEAD + h) * TSEQ + t1) * HDIM + d0] = lo;
            *(float2*)&dst[((size_t)(n * NHEAD + h) * TSEQ + t2) * HDIM + d0] = hi;
        }
    }
}

// ---------------------------------------------------------------------------
// Kernel 2a: TENSOR-CORE split-K causal flash attention, full tf32
// (R15-proven). Smem: Qs[32][136]@0, Ks[32][136]@4352, Vs[128][40]@8704,
// Ps[64][136]@13824 -> 90112 B.
// ---------------------------------------------------------------------------
#define ATT_SMEM 90112

__global__ __launch_bounds__(256) void attn_tc() {
    extern __shared__ float sm[];
    float* Qs = sm;                 // stride 136
    float* Ks = sm + 4352;          // stride 136
    float* Vs = sm + 8704;          // stride 40
    float* Ps = sm + 13824;         // stride 136

    int x = blockIdx.x;
    int qt = 0, ubase = 0;
    while (x >= ubase + qt + 1) { ubase += qt + 1; qt++; }
    const int p = x - ubase;
    const int nh = blockIdx.y;
    const int tid = threadIdx.x;
    const int lane = tid & 31;
    const int wm = tid >> 5;
    const int g = lane >> 2, tig = lane & 3;
    const int bq = qt * 128;

    // ---- fills (rounded to tf32) ----
    {
        const int q = tid >> 1, dh = (tid & 1) * 16;
        const float* src = g_q + ((size_t)nh * TSEQ + bq + q) * HDIM + dh;
        const float sc = 0.17677669529663687f;
        #pragma unroll
        for (int i = 0; i < 4; i++) {
            float4 v = *(const float4*)(src + i * 4);
            Qs[(dh + i * 4 + 0) * 136 + q] = tf32f(v.x * sc);
            Qs[(dh + i * 4 + 1) * 136 + q] = tf32f(v.y * sc);
            Qs[(dh + i * 4 + 2) * 136 + q] = tf32f(v.z * sc);
            Qs[(dh + i * 4 + 3) * 136 + q] = tf32f(v.w * sc);
        }
    }
    {
        const int k = tid >> 1, dh = (tid & 1) * 16;
        const float* src = g_k + ((size_t)nh * TSEQ + p * 128 + k) * HDIM + dh;
        #pragma unroll
        for (int i = 0; i < 4; i++) {
            float4 v = *(const float4*)(src + i * 4);
            Ks[(dh + i * 4 + 0) * 136 + k] = tf32f(v.x);
            Ks[(dh + i * 4 + 1) * 136 + k] = tf32f(v.y);
            Ks[(dh + i * 4 + 2) * 136 + k] = tf32f(v.z);
            Ks[(dh + i * 4 + 3) * 136 + k] = tf32f(v.w);
        }
    }
    {
        const int k = tid >> 1, dh = (tid & 1) * 16;
        const float* src = g_v + ((size_t)nh * TSEQ + p * 128 + k) * HDIM + dh;
        #pragma unroll
        for (int i = 0; i < 4; i++) {
            float4 v = *(const float4*)(src + i * 4);
            *(float4*)&Vs[k * 40 + dh + i * 4] = round4(v);
        }
    }
    __syncthreads();

    float o_acc[4][4];
    #pragma unroll
    for (int an = 0; an < 4; an++)
        #pragma unroll
        for (int i = 0; i < 4; i++) o_acc[an][i] = 0.0f;
    float ls0 = 0.0f, ls1 = 0.0f;

    const int mq = wm * 16;
    const int q0 = bq + mq + g;
    const bool diag = (p == qt);

    #pragma unroll
    for (int chunk = 0; chunk < 2; chunk++) {
        const int ck = chunk * 64;

        float s[8][4];
        #pragma unroll
        for (int an = 0; an < 8; an++)
            #pragma unroll
            for (int i = 0; i < 4; i++) s[an][i] = 0.0f;

        #pragma unroll
        for (int ks = 0; ks < 4; ks++) {
            const int kr0 = ks * 8 + tig, kr1 = kr0 + 4;
            unsigned a[4];
            a[0] = __float_as_uint(Qs[kr0 * 136 + mq + g]);
            a[1] = __float_as_uint(Qs[kr0 * 136 + mq + g + 8]);
            a[2] = __float_as_uint(Qs[kr1 * 136 + mq + g]);
            a[3] = __float_as_uint(Qs[kr1 * 136 + mq + g + 8]);
            #pragma unroll
            for (int an = 0; an < 8; an++) {
                unsigned b0 = __float_as_uint(Ks[kr0 * 136 + ck + an * 8 + g]);
                unsigned b1 = __float_as_uint(Ks[kr1 * 136 + ck + an * 8 + g]);
                mma_tf32(s[an], a[0], a[1], a[2], a[3], b0, b1);
            }
        }

        #pragma unroll
        for (int an = 0; an < 8; an++) {
            float e0 = tf32f(__expf(s[an][0]));
            float e1 = tf32f(__expf(s[an][1]));
            float e2 = tf32f(__expf(s[an][2]));
            float e3 = tf32f(__expf(s[an][3]));
            if (diag) {
                const int key0 = p * 128 + ck + an * 8 + 2 * tig;
                if (key0     > q0)     e0 = 0.0f;
                if (key0 + 1 > q0)     e1 = 0.0f;
                if (key0     > q0 + 8) e2 = 0.0f;
                if (key0 + 1 > q0 + 8) e3 = 0.0f;
            }
            ls0 += e0 + e1;
            ls1 += e2 + e3;
            const int kl = an * 8 + 2 * tig;
            Ps[(kl    ) * 136 + mq + g    ] = e0;
            Ps[(kl + 1) * 136 + mq + g    ] = e1;
            Ps[(kl    ) * 136 + mq + g + 8] = e2;
            Ps[(kl + 1) * 136 + mq + g + 8] = e3;
        }
        __syncwarp();

        #pragma unroll
        for (int ks = 0; ks < 8; ks++) {
            const int kr0 = ks * 8 + tig, kr1 = kr0 + 4;
            unsigned ph[4];
            ph[0] = __float_as_uint(Ps[kr0 * 136 + mq + g]);
            ph[1] = __float_as_uint(Ps[kr0 * 136 + mq + g + 8]);
            ph[2] = __float_as_uint(Ps[kr1 * 136 + mq + g]);
            ph[3] = __float_as_uint(Ps[kr1 * 136 + mq + g + 8]);
            const int vr0 = ck + kr0, vr1 = ck + kr1;
            #pragma unroll
            for (int an = 0; an < 4; an++) {
                unsigned b0 = __float_as_uint(Vs[vr0 * 40 + an * 8 + g]);
                unsigned b1 = __float_as_uint(Vs[vr1 * 40 + an * 8 + g]);
                mma_tf32(o_acc[an], ph[0], ph[1], ph[2], ph[3], b0, b1);
            }
        }
        __syncwarp();
    }

    float* pout = g_pacc + ((size_t)(nh * 36 + blockIdx.x) * 32) * 128;
    #pragma unroll
    for (int an = 0; an < 4; an++) {
        const int d0 = an * 8 + 2 * tig;
        const int ql = mq + g;
        pout[(d0    ) * 128 + ql    ] = o_acc[an][0];
        pout[(d0 + 1) * 128 + ql    ] = o_acc[an][1];
        pout[(d0    ) * 128 + ql + 8] = o_acc[an][2];
        pout[(d0 + 1) * 128 + ql + 8] = o_acc[an][3];
    }
    ls0 += __shfl_xor_sync(0xFFFFFFFF, ls0, 1);
    ls0 += __shfl_xor_sync(0xFFFFFFFF, ls0, 2);
    ls1 += __shfl_xor_sync(0xFFFFFFFF, ls1, 1);
    ls1 += __shfl_xor_sync(0xFFFFFFFF, ls1, 2);
    if (tig == 0) {
        float* lout = g_plsum + (size_t)(nh * 36 + blockIdx.x) * 128;
        lout[mq + g]     = ls0;
        lout[mq + g + 8] = ls1;
    }
}

// ---------------------------------------------------------------------------
// Kernel 2b: per-query inverse lsum (R11-proven).
// ---------------------------------------------------------------------------
__global__ __launch_bounds__(256) void attn_inv() {
    const int t = blockIdx.x * 256 + threadIdx.x;
    const int q  = t & 127;
    const int qt = (t >> 7) & 7;
    const int nh = t >> 10;
    const int base = qt * (qt + 1) / 2;

    float lsum = 0.0f;
    for (int p = 0; p <= qt; p++)
        lsum += g_plsum[(size_t)(nh * 36 + base + p) * 128 + q];
    g_inv[t] = 1.0f / lsum;
}

// ---------------------------------------------------------------------------
// Kernel 2c: element-parallel reduce -> g_attn, FLOAT4 over q.
// 524288 threads (2048 blocks x 256): thread = (nh, qt, d, q4).
// ---------------------------------------------------------------------------
__global__ __launch_bounds__(256) void attn_reduce2() {
    const int t = blockIdx.x * 256 + threadIdx.x;   // 524288 total
    const int q4 = t & 31;          // 32 groups of 4 q
    const int d  = (t >> 5) & 31;
    const int qt = (t >> 10) & 7;
    const int nh = t >> 13;
    const int base = qt * (qt + 1) / 2;
    const int q = q4 * 4;

    float4 acc = make_float4(0.f, 0.f, 0.f, 0.f);
    const float* pin = g_pacc + ((size_t)(nh * 36 + base) * 32 + d) * 128 + q;
    #pragma unroll 4
    for (int p = 0; p <= qt; p++) {
        float4 v = *(const float4*)(pin + (size_t)p * 32 * 128);
        acc.x += v.x; acc.y += v.y; acc.z += v.z; acc.w += v.w;
    }

    float4 inv = *(const float4*)&g_inv[(nh * 8 + qt) * 128 + q];
    const int n = nh >> 3;
    const int h = nh & 7;
    const int tq = qt * 128 + q;
    float4 r = make_float4(acc.x * inv.x, acc.y * inv.y, acc.z * inv.z, acc.w * inv.w);
    *(float4*)&g_attn[(size_t)(h * HDIM + d) * (NBATCH * TSEQ) + (size_t)n * TSEQ + tq] = r;
}

// ---------------------------------------------------------------------------
// Kernel 3: mix + bias + residual, SINGLE-TERM tf32 (error diluted by the
// image residual exactly like the attention path — see R16 theory).
// ---------------------------------------------------------------------------
__global__ __launch_bounds__(256) void mix_mma(const float* __restrict__ image,
                                               const float* __restrict__ w,
                                               const float* __restrict__ bias,
                                               float* __restrict__ out) {
    __shared__ float As[16 * AS_STRIDE];
    __shared__ float Bs[16 * BS_STRIDE];
    const int tid = threadIdx.x;
    const int lane = tid & 31;
    const int wid = tid >> 5;
    const int wm = wid & 3;
    const int wn = wid >> 2;
    const int g = lane >> 2, tig = lane & 3;
    const int bm = blockIdx.y * 128;
    const int bn = blockIdx.x * 64;
    const int n  = bm >> 10;
    const int t0 = bm & 1023;

    float c[2][4][4];
    #pragma unroll
    for (int am = 0; am < 2; am++)
        #pragma unroll
        for (int an = 0; an < 4; an++)
            #pragma unroll
            for (int i = 0; i < 4; i++) c[am][an][i] = 0.0f;

    float4 pa[2], pb;
    {
        #pragma unroll
        for (int l = 0; l < 2; l++) {
            int idx = l * 256 + tid;
            int k = idx >> 5, f = idx & 31;
            pa[l] = *(const float4*)&g_attn[(size_t)k * 8192 + bm + f * 4];
        }
        int k = tid >> 4, f = tid & 15;
        pb = *(const float4*)&w[k * 256 + bn + f * 4];
    }

    for (int k0 = 0; k0 < 256; k0 += 16) {
        #pragma unroll
        for (int l = 0; l < 2; l++) {
            int idx = l * 256 + tid;
            int k = idx >> 5, f = idx & 31;
            *(float4*)&As[k * AS_STRIDE + f * 4] = round4(pa[l]);
        }
        {
            int k = tid >> 4, f = tid & 15;
            *(float4*)&Bs[k * BS_STRIDE + f * 4] = round4(pb);
        }
        __syncthreads();
        if (k0 + 16 < 256) {
            #pragma unroll
            for (int l = 0; l < 2; l++) {
                int idx = l * 256 + tid;
                int k = idx >> 5, f = idx & 31;
                pa[l] = *(const float4*)&g_attn[(size_t)(k0 + 16 + k) * 8192 + bm + f * 4];
            }
            int k = tid >> 4, f = tid & 15;
            pb = *(const float4*)&w[(k0 + 16 + k) * 256 + bn + f * 4];
        }
        #pragma unroll
        for (int ks = 0; ks < 16; ks += 8) {
            unsigned a[2][4], b[4][2];
            #pragma unroll
            for (int am = 0; am < 2; am++) {
                const int mb = wm * 32 + am * 16;
                a[am][0] = __float_as_uint(As[(ks + tig) * AS_STRIDE + mb + g]);
                a[am][1] = __float_as_uint(As[(ks + tig) * AS_STRIDE + mb + g + 8]);
                a[am][2] = __float_as_uint(As[(ks + tig + 4) * AS_STRIDE + mb + g]);
                a[am][3] = __float_as_uint(As[(ks + tig + 4) * AS_STRIDE + mb + g + 8]);
            }
            #pragma unroll
            for (int an = 0; an < 4; an++) {
                const int nb = wn * 32 + an * 8;
                b[an][0] = __float_as_uint(Bs[(ks + tig) * BS_STRIDE + nb + g]);
                b[an][1] = __float_as_uint(Bs[(ks + tig + 4) * BS_STRIDE + nb + g]);
            }
            #pragma unroll
            for (int am = 0; am < 2; am++)
                #pragma unroll
                for (int an = 0; an < 4; an++)
                    mma_tf32(c[am][an], a[am][0], a[am][1], a[am][2], a[am][3],
                             b[an][0], b[an][1]);
        }
        __syncthreads();
    }

    #pragma unroll
    for (int an = 0; an < 4; an++) {
        const int o = bn + wn * 32 + an * 8 + 2 * tig;
        const float2 b2 = *(const float2*)&bias[o];
        #pragma unroll
        for (int am = 0; am < 2; am++) {
            const int r0 = wm * 32 + am * 16 + g;
            const int t1 = t0 + r0;
            const size_t g00 = (size_t)n * 262144 + (size_t)o * 1024 + t1;
            const size_t g01 = g00 + 1024;
            out[g00]     = c[am][an][0] + b2.x + image[g00];
            out[g01]     = c[am][an][1] + b2.y + image[g01];
            out[g00 + 8] = c[am][an][2] + b2.x + image[g00 + 8];
            out[g01 + 8] = c[am][an][3] + b2.y + image[g01 + 8];
        }
    }
}

// ---------------------------------------------------------------------------
extern "C" void kernel_launch(void* const* d_in, const int* in_sizes, int n_in,
                              void* d_out, int out_size) {
    const float* image = (const float*)d_in[0];
    const float* w_kqv = (const float*)d_in[1];
    const float* b_kqv = (const float*)d_in[2];
    const float* w_mix = (const float*)d_in[3];
    const float* b_mix = (const float*)d_in[4];
    float* out = (float*)d_out;

    cudaFuncSetAttribute(attn_tc, cudaFuncAttributeMaxDynamicSharedMemorySize,
                         ATT_SMEM);

    dim3 gridA(768 / 64, 8192 / 128);
    kqv_mma<<<gridA, 256>>>(image, w_kqv, b_kqv);

    dim3 gridB(36, 64);
    attn_tc<<<gridB, 256, ATT_SMEM>>>();

    attn_inv<<<256, 256>>>();
    attn_reduce2<<<2048, 256>>>();

    dim3 gridC(256 / 64, 8192 / 128);
    mix_mma<<<gridC, 256>>>(image, w_mix, b_mix, out);
}

// round 17
// speedup vs baseline: 2.2969x; 1.0299x over previous
#include <cuda_runtime.h>
#include <math.h>

// Problem constants
#define NBATCH 8
#define CCH    256
#define TSEQ   1024
#define NHEAD  8
#define HDIM   32

// ---- tf32 mma primitives ----
__device__ __forceinline__ unsigned tf32_of(float x) {
    unsigned r; asm("cvt.rna.tf32.f32 %0, %1;" : "=r"(r) : "f"(x)); return r;
}
__device__ __forceinline__ float tf32f(float x) {
    return __uint_as_float(tf32_of(x));
}
__device__ __forceinline__ void mma_tf32(float c[4],
                                         unsigned a0, unsigned a1, unsigned a2, unsigned a3,
                                         unsigned b0, unsigned b1) {
    asm("mma.sync.aligned.m16n8k8.row.col.f32.tf32.tf32.f32 "
        "{%0,%1,%2,%3}, {%4,%5,%6,%7}, {%8,%9}, {%0,%1,%2,%3};"
        : "+f"(c[0]), "+f"(c[1]), "+f"(c[2]), "+f"(c[3])
        : "r"(a0), "r"(a1), "r"(a2), "r"(a3), "r"(b0), "r"(b1));
}
// round a float4 to tf32 bit patterns (as floats)
__device__ __forceinline__ float4 round4(float4 v) {
    return make_float4(tf32f(v.x), tf32f(v.y), tf32f(v.z), tf32f(v.w));
}

// Scratch. K/Q/V in [N, H, T, D]. g_attn TRANSPOSED: [C, N*T].
__device__ float g_k[NBATCH * NHEAD * TSEQ * HDIM];
__device__ float g_q[NBATCH * NHEAD * TSEQ * HDIM];
__device__ float g_v[NBATCH * NHEAD * TSEQ * HDIM];
__device__ float g_attn[CCH * NBATCH * TSEQ];
// Split-K partials: 36 units/nh of 128 queries x 128 keys.
__device__ float g_pacc[64 * 36 * 32 * 128];
__device__ float g_plsum[64 * 36 * 128];

#define AS_STRIDE 136
#define BS_STRIDE 72

// ---------------------------------------------------------------------------
// Kernel 1: KQV projection, single-term tf32, RE-TILED:
// block 128m x 128n (grid 6 x 64), warp tile 32m x 64n (am=2, an=8).
// Per ks-step: 8 A-LDS + 16 B-LDS per 16 mma (was 16 LDS per 8 mma).
// ---------------------------------------------------------------------------
__global__ __launch_bounds__(256) void kqv_mma(const float* __restrict__ image,
                                               const float* __restrict__ w,
                                               const float* __restrict__ bias) {
    __shared__ float As[16 * AS_STRIDE];
    __shared__ float Bs[16 * AS_STRIDE];   // 128-wide B tile, stride 136
    const int tid = threadIdx.x;
    const int lane = tid & 31;
    const int wid = tid >> 5;
    const int wm = wid & 3;        // 4 m-warps x 32 rows
    const int wn = wid >> 2;       // 2 n-warps x 64 cols
    const int g = lane >> 2, tig = lane & 3;
    const int bm = blockIdx.y * 128;
    const int bn = blockIdx.x * 128;
    const int n  = bm >> 10;
    const int t0 = bm & 1023;

    float c[2][8][4];
    #pragma unroll
    for (int am = 0; am < 2; am++)
        #pragma unroll
        for (int an = 0; an < 8; an++)
            #pragma unroll
            for (int i = 0; i < 4; i++) c[am][an][i] = 0.0f;

    float4 pa[2], pb[2];
    {
        #pragma unroll
        for (int l = 0; l < 2; l++) {
            int idx = l * 256 + tid;
            int k = idx >> 5, f = idx & 31;
            pa[l] = *(const float4*)&image[n * 262144 + k * 1024 + t0 + f * 4];
            pb[l] = *(const float4*)&w[k * 768 + bn + f * 4];
        }
    }

    for (int k0 = 0; k0 < 256; k0 += 16) {
        #pragma unroll
        for (int l = 0; l < 2; l++) {
            int idx = l * 256 + tid;
            int k = idx >> 5, f = idx & 31;
            *(float4*)&As[k * AS_STRIDE + f * 4] = round4(pa[l]);
            *(float4*)&Bs[k * AS_STRIDE + f * 4] = round4(pb[l]);
        }
        __syncthreads();
        if (k0 + 16 < 256) {
            #pragma unroll
            for (int l = 0; l < 2; l++) {
                int idx = l * 256 + tid;
                int k = idx >> 5, f = idx & 31;
                pa[l] = *(const float4*)&image[n * 262144 + (k0 + 16 + k) * 1024 + t0 + f * 4];
                pb[l] = *(const float4*)&w[(k0 + 16 + k) * 768 + bn + f * 4];
            }
        }
        #pragma unroll
        for (int ks = 0; ks < 16; ks += 8) {
            unsigned a[2][4], b[8][2];
            #pragma unroll
            for (int am = 0; am < 2; am++) {
                const int mb = wm * 32 + am * 16;
                a[am][0] = __float_as_uint(As[(ks + tig) * AS_STRIDE + mb + g]);
                a[am][1] = __float_as_uint(As[(ks + tig) * AS_STRIDE + mb + g + 8]);
                a[am][2] = __float_as_uint(As[(ks + tig + 4) * AS_STRIDE + mb + g]);
                a[am][3] = __float_as_uint(As[(ks + tig + 4) * AS_STRIDE + mb + g + 8]);
            }
            #pragma unroll
            for (int an = 0; an < 8; an++) {
                const int nb = wn * 64 + an * 8;
                b[an][0] = __float_as_uint(Bs[(ks + tig) * AS_STRIDE + nb + g]);
                b[an][1] = __float_as_uint(Bs[(ks + tig + 4) * AS_STRIDE + nb + g]);
            }
            #pragma unroll
            for (int am = 0; am < 2; am++)
                #pragma unroll
                for (int an = 0; an < 8; an++)
                    mma_tf32(c[am][an], a[am][0], a[am][1], a[am][2], a[am][3],
                             b[an][0], b[an][1]);
        }
        __syncthreads();
    }

    #pragma unroll
    for (int an = 0; an < 8; an++) {
        const int o = bn + wn * 64 + an * 8 + 2 * tig;
        const float2 b2 = *(const float2*)&bias[o];
        const int which = o >> 8;
        const int cc = o & 255;
        const int h = cc >> 5;
        const int d0 = cc & 31;
        float* dst = (which == 0) ? g_k : (which == 1) ? g_q : g_v;
        #pragma unroll
        for (int am = 0; am < 2; am++) {
            const int r0 = wm * 32 + am * 16 + g;
            const int t1 = t0 + r0;
            const int t2 = t1 + 8;
            float2 lo = make_float2(c[am][an][0] + b2.x, c[am][an][1] + b2.y);
            float2 hi = make_float2(c[am][an][2] + b2.x, c[am][an][3] + b2.y);
            *(float2*)&dst[((size_t)(n * NHEAD + h) * TSEQ + t1) * HDIM + d0] = lo;
            *(float2*)&dst[((size_t)(n * NHEAD + h) * TSEQ + t2) * HDIM + d0] = hi;
        }
    }
}

// ---------------------------------------------------------------------------
// Kernel 2a: TENSOR-CORE split-K causal flash attention, full tf32
// (R15/R16-proven). Smem: Qs[32][136]@0, Ks[32][136]@4352, Vs[128][40]@8704,
// Ps[64][136]@13824 -> 90112 B.
// ---------------------------------------------------------------------------
#define ATT_SMEM 90112

__global__ __launch_bounds__(256) void attn_tc() {
    extern __shared__ float sm[];
    float* Qs = sm;                 // stride 136
    float* Ks = sm + 4352;          // stride 136
    float* Vs = sm + 8704;          // stride 40
    float* Ps = sm + 13824;         // stride 136

    int x = blockIdx.x;
    int qt = 0, ubase = 0;
    while (x >= ubase + qt + 1) { ubase += qt + 1; qt++; }
    const int p = x - ubase;
    const int nh = blockIdx.y;
    const int tid = threadIdx.x;
    const int lane = tid & 31;
    const int wm = tid >> 5;
    const int g = lane >> 2, tig = lane & 3;
    const int bq = qt * 128;

    // ---- fills (rounded to tf32) ----
    {
        const int q = tid >> 1, dh = (tid & 1) * 16;
        const float* src = g_q + ((size_t)nh * TSEQ + bq + q) * HDIM + dh;
        const float sc = 0.17677669529663687f;
        #pragma unroll
        for (int i = 0; i < 4; i++) {
            float4 v = *(const float4*)(src + i * 4);
            Qs[(dh + i * 4 + 0) * 136 + q] = tf32f(v.x * sc);
            Qs[(dh + i * 4 + 1) * 136 + q] = tf32f(v.y * sc);
            Qs[(dh + i * 4 + 2) * 136 + q] = tf32f(v.z * sc);
            Qs[(dh + i * 4 + 3) * 136 + q] = tf32f(v.w * sc);
        }
    }
    {
        const int k = tid >> 1, dh = (tid & 1) * 16;
        const float* src = g_k + ((size_t)nh * TSEQ + p * 128 + k) * HDIM + dh;
        #pragma unroll
        for (int i = 0; i < 4; i++) {
            float4 v = *(const float4*)(src + i * 4);
            Ks[(dh + i * 4 + 0) * 136 + k] = tf32f(v.x);
            Ks[(dh + i * 4 + 1) * 136 + k] = tf32f(v.y);
            Ks[(dh + i * 4 + 2) * 136 + k] = tf32f(v.z);
            Ks[(dh + i * 4 + 3) * 136 + k] = tf32f(v.w);
        }
    }
    {
        const int k = tid >> 1, dh = (tid & 1) * 16;
        const float* src = g_v + ((size_t)nh * TSEQ + p * 128 + k) * HDIM + dh;
        #pragma unroll
        for (int i = 0; i < 4; i++) {
            float4 v = *(const float4*)(src + i * 4);
            *(float4*)&Vs[k * 40 + dh + i * 4] = round4(v);
        }
    }
    __syncthreads();

    float o_acc[4][4];
    #pragma unroll
    for (int an = 0; an < 4; an++)
        #pragma unroll
        for (int i = 0; i < 4; i++) o_acc[an][i] = 0.0f;
    float ls0 = 0.0f, ls1 = 0.0f;

    const int mq = wm * 16;
    const int q0 = bq + mq + g;
    const bool diag = (p == qt);

    #pragma unroll
    for (int chunk = 0; chunk < 2; chunk++) {
        const int ck = chunk * 64;

        float s[8][4];
        #pragma unroll
        for (int an = 0; an < 8; an++)
            #pragma unroll
            for (int i = 0; i < 4; i++) s[an][i] = 0.0f;

        #pragma unroll
        for (int ks = 0; ks < 4; ks++) {
            const int kr0 = ks * 8 + tig, kr1 = kr0 + 4;
            unsigned a[4];
            a[0] = __float_as_uint(Qs[kr0 * 136 + mq + g]);
            a[1] = __float_as_uint(Qs[kr0 * 136 + mq + g + 8]);
            a[2] = __float_as_uint(Qs[kr1 * 136 + mq + g]);
            a[3] = __float_as_uint(Qs[kr1 * 136 + mq + g + 8]);
            #pragma unroll
            for (int an = 0; an < 8; an++) {
                unsigned b0 = __float_as_uint(Ks[kr0 * 136 + ck + an * 8 + g]);
                unsigned b1 = __float_as_uint(Ks[kr1 * 136 + ck + an * 8 + g]);
                mma_tf32(s[an], a[0], a[1], a[2], a[3], b0, b1);
            }
        }

        #pragma unroll
        for (int an = 0; an < 8; an++) {
            float e0 = tf32f(__expf(s[an][0]));
            float e1 = tf32f(__expf(s[an][1]));
            float e2 = tf32f(__expf(s[an][2]));
            float e3 = tf32f(__expf(s[an][3]));
            if (diag) {
                const int key0 = p * 128 + ck + an * 8 + 2 * tig;
                if (key0     > q0)     e0 = 0.0f;
                if (key0 + 1 > q0)     e1 = 0.0f;
                if (key0     > q0 + 8) e2 = 0.0f;
                if (key0 + 1 > q0 + 8) e3 = 0.0f;
            }
            ls0 += e0 + e1;
            ls1 += e2 + e3;
            const int kl = an * 8 + 2 * tig;
            Ps[(kl    ) * 136 + mq + g    ] = e0;
            Ps[(kl + 1) * 136 + mq + g    ] = e1;
            Ps[(kl    ) * 136 + mq + g + 8] = e2;
            Ps[(kl + 1) * 136 + mq + g + 8] = e3;
        }
        __syncwarp();

        #pragma unroll
        for (int ks = 0; ks < 8; ks++) {
            const int kr0 = ks * 8 + tig, kr1 = kr0 + 4;
            unsigned ph[4];
            ph[0] = __float_as_uint(Ps[kr0 * 136 + mq + g]);
            ph[1] = __float_as_uint(Ps[kr0 * 136 + mq + g + 8]);
            ph[2] = __float_as_uint(Ps[kr1 * 136 + mq + g]);
            ph[3] = __float_as_uint(Ps[kr1 * 136 + mq + g + 8]);
            const int vr0 = ck + kr0, vr1 = ck + kr1;
            #pragma unroll
            for (int an = 0; an < 4; an++) {
                unsigned b0 = __float_as_uint(Vs[vr0 * 40 + an * 8 + g]);
                unsigned b1 = __float_as_uint(Vs[vr1 * 40 + an * 8 + g]);
                mma_tf32(o_acc[an], ph[0], ph[1], ph[2], ph[3], b0, b1);
            }
        }
        __syncwarp();
    }

    float* pout = g_pacc + ((size_t)(nh * 36 + blockIdx.x) * 32) * 128;
    #pragma unroll
    for (int an = 0; an < 4; an++) {
        const int d0 = an * 8 + 2 * tig;
        const int ql = mq + g;
        pout[(d0    ) * 128 + ql    ] = o_acc[an][0];
        pout[(d0 + 1) * 128 + ql    ] = o_acc[an][1];
        pout[(d0    ) * 128 + ql + 8] = o_acc[an][2];
        pout[(d0 + 1) * 128 + ql + 8] = o_acc[an][3];
    }
    ls0 += __shfl_xor_sync(0xFFFFFFFF, ls0, 1);
    ls0 += __shfl_xor_sync(0xFFFFFFFF, ls0, 2);
    ls1 += __shfl_xor_sync(0xFFFFFFFF, ls1, 1);
    ls1 += __shfl_xor_sync(0xFFFFFFFF, ls1, 2);
    if (tig == 0) {
        float* lout = g_plsum + (size_t)(nh * 36 + blockIdx.x) * 128;
        lout[mq + g]     = ls0;
        lout[mq + g + 8] = ls1;
    }
}

// ---------------------------------------------------------------------------
// Kernel 2b: element-parallel reduce with FUSED lsum reduction + divide.
// 524288 threads (2048 x 256): thread = (nh, qt, d, q4), float4 over q.
// lsum loads are L1/L2-hot (1.2MB array, shared across the 32 d-threads).
// ---------------------------------------------------------------------------
__global__ __launch_bounds__(256) void attn_reduce2() {
    const int t = blockIdx.x * 256 + threadIdx.x;   // 524288 total
    const int q4 = t & 31;
    const int d  = (t >> 5) & 31;
    const int qt = (t >> 10) & 7;
    const int nh = t >> 13;
    const int base = qt * (qt + 1) / 2;
    const int q = q4 * 4;

    float4 acc = make_float4(0.f, 0.f, 0.f, 0.f);
    float4 ls  = make_float4(0.f, 0.f, 0.f, 0.f);
    const float* pin = g_pacc + ((size_t)(nh * 36 + base) * 32 + d) * 128 + q;
    const float* lin = g_plsum + (size_t)(nh * 36 + base) * 128 + q;
    #pragma unroll 4
    for (int p = 0; p <= qt; p++) {
        float4 v = *(const float4*)(pin + (size_t)p * 32 * 128);
        float4 l = *(const float4*)(lin + (size_t)p * 128);
        acc.x += v.x; acc.y += v.y; acc.z += v.z; acc.w += v.w;
        ls.x  += l.x; ls.y  += l.y; ls.z  += l.z; ls.w  += l.w;
    }

    const int n = nh >> 3;
    const int h = nh & 7;
    const int tq = qt * 128 + q;
    float4 r = make_float4(acc.x / ls.x, acc.y / ls.y, acc.z / ls.z, acc.w / ls.w);
    *(float4*)&g_attn[(size_t)(h * HDIM + d) * (NBATCH * TSEQ) + (size_t)n * TSEQ + tq] = r;
}

// ---------------------------------------------------------------------------
// Kernel 3: mix + bias + residual, single-term tf32 (R16-proven).
// ---------------------------------------------------------------------------
__global__ __launch_bounds__(256) void mix_mma(const float* __restrict__ image,
                                               const float* __restrict__ w,
                                               const float* __restrict__ bias,
                                               float* __restrict__ out) {
    __shared__ float As[16 * AS_STRIDE];
    __shared__ float Bs[16 * BS_STRIDE];
    const int tid = threadIdx.x;
    const int lane = tid & 31;
    const int wid = tid >> 5;
    const int wm = wid & 3;
    const int wn = wid >> 2;
    const int g = lane >> 2, tig = lane & 3;
    const int bm = blockIdx.y * 128;
    const int bn = blockIdx.x * 64;
    const int n  = bm >> 10;
    const int t0 = bm & 1023;

    float c[2][4][4];
    #pragma unroll
    for (int am = 0; am < 2; am++)
        #pragma unroll
        for (int an = 0; an < 4; an++)
            #pragma unroll
            for (int i = 0; i < 4; i++) c[am][an][i] = 0.0f;

    float4 pa[2], pb;
    {
        #pragma unroll
        for (int l = 0; l < 2; l++) {
            int idx = l * 256 + tid;
            int k = idx >> 5, f = idx & 31;
            pa[l] = *(const float4*)&g_attn[(size_t)k * 8192 + bm + f * 4];
        }
        int k = tid >> 4, f = tid & 15;
        pb = *(const float4*)&w[k * 256 + bn + f * 4];
    }

    for (int k0 = 0; k0 < 256; k0 += 16) {
        #pragma unroll
        for (int l = 0; l < 2; l++) {
            int idx = l * 256 + tid;
            int k = idx >> 5, f = idx & 31;
            *(float4*)&As[k * AS_STRIDE + f * 4] = round4(pa[l]);
        }
        {
            int k = tid >> 4, f = tid & 15;
            *(float4*)&Bs[k * BS_STRIDE + f * 4] = round4(pb);
        }
        __syncthreads();
        if (k0 + 16 < 256) {
            #pragma unroll
            for (int l = 0; l < 2; l++) {
                int idx = l * 256 + tid;
                int k = idx >> 5, f = idx & 31;
                pa[l] = *(const float4*)&g_attn[(size_t)(k0 + 16 + k) * 8192 + bm + f * 4];
            }
            int k = tid >> 4, f = tid & 15;
            pb = *(const float4*)&w[(k0 + 16 + k) * 256 + bn + f * 4];
        }
        #pragma unroll
        for (int ks = 0; ks < 16; ks += 8) {
            unsigned a[2][4], b[4][2];
            #pragma unroll
            for (int am = 0; am < 2; am++) {
                const int mb = wm * 32 + am * 16;
                a[am][0] = __float_as_uint(As[(ks + tig) * AS_STRIDE + mb + g]);
                a[am][1] = __float_as_uint(As[(ks + tig) * AS_STRIDE + mb + g + 8]);
                a[am][2] = __float_as_uint(As[(ks + tig + 4) * AS_STRIDE + mb + g]);
                a[am][3] = __float_as_uint(As[(ks + tig + 4) * AS_STRIDE + mb + g + 8]);
            }
            #pragma unroll
            for (int an = 0; an < 4; an++) {
                const int nb = wn * 32 + an * 8;
                b[an][0] = __float_as_uint(Bs[(ks + tig) * BS_STRIDE + nb + g]);
                b[an][1] = __float_as_uint(Bs[(ks + tig + 4) * BS_STRIDE + nb + g]);
            }
            #pragma unroll
            for (int am = 0; am < 2; am++)
                #pragma unroll
                for (int an = 0; an < 4; an++)
                    mma_tf32(c[am][an], a[am][0], a[am][1], a[am][2], a[am][3],
                             b[an][0], b[an][1]);
        }
        __syncthreads();
    }

    #pragma unroll
    for (int an = 0; an < 4; an++) {
        const int o = bn + wn * 32 + an * 8 + 2 * tig;
        const float2 b2 = *(const float2*)&bias[o];
        #pragma unroll
        for (int am = 0; am < 2; am++) {
            const int r0 = wm * 32 + am * 16 + g;
            const int t1 = t0 + r0;
            const size_t g00 = (size_t)n * 262144 + (size_t)o * 1024 + t1;
            const size_t g01 = g00 + 1024;
            out[g00]     = c[am][an][0] + b2.x + image[g00];
            out[g01]     = c[am][an][1] + b2.y + image[g01];
            out[g00 + 8] = c[am][an][2] + b2.x + image[g00 + 8];
            out[g01 + 8] = c[am][an][3] + b2.y + image[g01 + 8];
        }
    }
}

// ---------------------------------------------------------------------------
extern "C" void kernel_launch(void* const* d_in, const int* in_sizes, int n_in,
                              void* d_out, int out_size) {
    const float* image = (const float*)d_in[0];
    const float* w_kqv = (const float*)d_in[1];
    const float* b_kqv = (const float*)d_in[2];
    const float* w_mix = (const float*)d_in[3];
    const float* b_mix = (const float*)d_in[4];
    float* out = (float*)d_out;

    cudaFuncSetAttribute(attn_tc, cudaFuncAttributeMaxDynamicSharedMemorySize,
                         ATT_SMEM);

    dim3 gridA(768 / 128, 8192 / 128);
    kqv_mma<<<gridA, 256>>>(image, w_kqv, b_kqv);

    dim3 gridB(36, 64);
    attn_tc<<<gridB, 256, ATT_SMEM>>>();

    attn_reduce2<<<2048, 256>>>();

    dim3 gridC(256 / 64, 8192 / 128);
    mix_mma<<<gridC, 256>>>(image, w_mix, b_mix, out);
}